// round 11
// baseline (speedup 1.0000x reference)
#include <cuda_runtime.h>
#include <cuda_bf16.h>
#include <math.h>
#include <stdint.h>

// Problem constants
#define BB   2
#define SS   1024
#define HH   4096
#define NH   32
#define NKV  8
#define HD   128
#define MROWS (BB*SS)          // 2048

// -------------------- scratch (device globals; no allocation) --------------------
__device__ float g_q  [MROWS * NH  * HD];   // 2048 x 4096
__device__ float g_k  [MROWS * NKV * HD];   // 2048 x 1024
__device__ float g_v  [MROWS * NKV * HD];   // 2048 x 1024
__device__ float g_ctx[MROWS * NH  * HD];   // 2048 x 4096
__device__ float g_xr [MROWS * HH];         // tf32-rounded x
__device__ float g_wt [HH * (NH * HD)];     // tf32-rounded weight scratch (reused)
__device__ float g_cos[SS * (HD/2)];
__device__ float g_sin[SS * (HD/2)];

__device__ __forceinline__ float to_tf32(float x) {
    float r;
    asm("cvt.rna.tf32.f32 %0, %1;" : "=f"(r) : "f"(x));
    return r;
}

__device__ __forceinline__ void mma_tf32(float& d0, float& d1, float& d2, float& d3,
                                         uint32_t a0, uint32_t a1, uint32_t a2, uint32_t a3,
                                         uint32_t b0, uint32_t b1) {
    asm volatile("mma.sync.aligned.m16n8k8.row.col.f32.tf32.tf32.f32 "
                 "{%0,%1,%2,%3},{%4,%5,%6,%7},{%8,%9},{%0,%1,%2,%3};"
                 : "+f"(d0), "+f"(d1), "+f"(d2), "+f"(d3)
                 : "r"(a0), "r"(a1), "r"(a2), "r"(a3), "r"(b0), "r"(b1));
}

#define CP_ASYNC16(saddr, gptr) \
    asm volatile("cp.async.cg.shared.global [%0], [%1], 16;" :: "r"(saddr), "l"(gptr))
#define CP_COMMIT() asm volatile("cp.async.commit_group;")
#define CP_WAIT2()  asm volatile("cp.async.wait_group 2;")
#define CP_WAIT1()  asm volatile("cp.async.wait_group 1;")
#define CP_WAIT0()  asm volatile("cp.async.wait_group 0;")

// ==================== TF32 tensor-core GEMM (cp.async 4-stage) ====================
// C[M,N] = A[M,K] @ B[K,N], row-major, inputs ALREADY tf32-rounded.
// 128x128 block, BK=32, 256 threads (8 warps), warp tile 64x32,
// mma.m16n8k8.tf32. 4-stage cp.async ring, one barrier per K-iter.

#define ASTRIDE 36    // floats; 144 B row (16B-aligned), conflict-free frag LDS
#define BSTRIDE 136   // floats; 544 B row
#define STG_FLOATS (128*ASTRIDE + 32*BSTRIDE)     // 8960 floats = 35840 B
#define NSTG 4
#define GEMM_SMEM (NSTG * STG_FLOATS * 4)         // 143360 B

__device__ __forceinline__ void stage_tile(int tid, float* smbase,
                                           const float* __restrict__ Ag,
                                           const float* __restrict__ Bg,
                                           int N, int K, int t) {
    float* As = smbase + (t & 3) * STG_FLOATS;
    float* Bs = As + 128 * ASTRIDE;
    const float* ag = Ag + t * 32;
    const float* bg = Bg + (size_t)(t * 32) * N;
#pragma unroll
    for (int i = 0; i < 4; ++i) {
        int e = tid + i * 256;
        int r = e >> 3, c = e & 7;          // A: 128 rows x 8 chunks
        unsigned d = (unsigned)__cvta_generic_to_shared(As + r * ASTRIDE + c * 4);
        CP_ASYNC16(d, ag + (size_t)r * K + c * 4);
    }
#pragma unroll
    for (int i = 0; i < 4; ++i) {
        int e = tid + i * 256;
        int r = e >> 5, c = e & 31;         // B: 32 rows x 32 chunks
        unsigned d = (unsigned)__cvta_generic_to_shared(Bs + r * BSTRIDE + c * 4);
        CP_ASYNC16(d, bg + (size_t)r * N + c * 4);
    }
    CP_COMMIT();
}

__global__ __launch_bounds__(256) void gemm_tf32(const float* __restrict__ A,
                                                 const float* __restrict__ B,
                                                 float* __restrict__ C,
                                                 int M, int N, int K, int rnd) {
    extern __shared__ float sm[];

    const int tid  = threadIdx.x;
    const int lane = tid & 31;
    const int w    = tid >> 5;
    const int g    = lane >> 2;
    const int tg   = lane & 3;
    const int wm   = (w & 1) * 64;
    const int wn   = (w >> 1) * 32;
    const int bm   = blockIdx.y * 128;
    const int bn   = blockIdx.x * 128;

    const float* Ag = A + (size_t)bm * K;
    const float* Bg = B + bn;
    const int T = K >> 5;

    stage_tile(tid, sm, Ag, Bg, N, K, 0);
    stage_tile(tid, sm, Ag, Bg, N, K, 1);
    stage_tile(tid, sm, Ag, Bg, N, K, 2);

    float acc[4][4][4];
#pragma unroll
    for (int mi = 0; mi < 4; ++mi)
#pragma unroll
        for (int ni = 0; ni < 4; ++ni)
#pragma unroll
            for (int c = 0; c < 4; ++c) acc[mi][ni][c] = 0.f;

    for (int t = 0; t < T; ++t) {
        if (t < T - 2)      CP_WAIT2();
        else if (t == T - 2) CP_WAIT1();
        else                 CP_WAIT0();
        __syncthreads();
        // single barrier per iter: issuing into (t+3)&3 == (t-1)&3 is safe
        // because this barrier orders it after everyone's compute(t-1).
        if (t + 3 < T) stage_tile(tid, sm, Ag, Bg, N, K, t + 3);

        const float* Ab = sm + (t & 3) * STG_FLOATS;
        const float* Bb = Ab + 128 * ASTRIDE;

#pragma unroll
        for (int ka = 0; ka < 4; ++ka) {
            const int k0 = ka * 8;
            uint32_t af[4][4], bf[4][2];
#pragma unroll
            for (int mi = 0; mi < 4; ++mi) {
                const float* p = Ab + (size_t)(wm + mi * 16 + g) * ASTRIDE + k0 + tg;
                af[mi][0] = __float_as_uint(p[0]);
                af[mi][1] = __float_as_uint(p[8 * ASTRIDE]);
                af[mi][2] = __float_as_uint(p[4]);
                af[mi][3] = __float_as_uint(p[8 * ASTRIDE + 4]);
            }
#pragma unroll
            for (int ni = 0; ni < 4; ++ni) {
                const float* p = Bb + (size_t)(k0 + tg) * BSTRIDE + wn + ni * 8 + g;
                bf[ni][0] = __float_as_uint(p[0]);
                bf[ni][1] = __float_as_uint(p[4 * BSTRIDE]);
            }
#pragma unroll
            for (int mi = 0; mi < 4; ++mi)
#pragma unroll
                for (int ni = 0; ni < 4; ++ni)
                    mma_tf32(acc[mi][ni][0], acc[mi][ni][1], acc[mi][ni][2], acc[mi][ni][3],
                             af[mi][0], af[mi][1], af[mi][2], af[mi][3],
                             bf[ni][0], bf[ni][1]);
        }
    }

    // ---- epilogue (optionally tf32-round: V feeds tf32 flash directly)
#pragma unroll
    for (int mi = 0; mi < 4; ++mi) {
        int r0 = bm + wm + mi * 16 + g;
#pragma unroll
        for (int ni = 0; ni < 4; ++ni) {
            int c0 = bn + wn + ni * 8 + 2 * tg;
            float o0 = acc[mi][ni][0], o1 = acc[mi][ni][1];
            float o2 = acc[mi][ni][2], o3 = acc[mi][ni][3];
            if (rnd) { o0 = to_tf32(o0); o1 = to_tf32(o1); o2 = to_tf32(o2); o3 = to_tf32(o3); }
            float2 v0 = {o0, o1};
            float2 v1 = {o2, o3};
            *(float2*)(C + (size_t)r0 * N + c0)       = v0;
            *(float2*)(C + (size_t)(r0 + 8) * N + c0) = v1;
        }
    }
}

// -------------------- tf32-rounded copy (x and weights) --------------------
__global__ void round_copy(const float* __restrict__ in, float* __restrict__ outp) {
    int i = blockIdx.x * 1024 + threadIdx.x;
    float4 v = ((const float4*)in)[i];
    v.x = to_tf32(v.x); v.y = to_tf32(v.y);
    v.z = to_tf32(v.z); v.w = to_tf32(v.w);
    ((float4*)outp)[i] = v;
}

// -------------------- RoPE cos/sin table --------------------
__global__ __launch_bounds__(1024) void rope_table_kernel() {
    __shared__ double sinv[64];
    const int tid = threadIdx.x;
    if (tid < 64) sinv[tid] = exp(-(double)tid / 64.0 * log(10000.0));
    __syncthreads();
    const int f = tid & 63;
    const int s = blockIdx.x * 16 + (tid >> 6);
    double a = (double)s * sinv[f];
    double q = rint(a * 0.15915494309189535);      // 1/(2*pi)
    float r = (float)(a - q * 6.283185307179586);  // in [-pi, pi]
    float sc, cc;
    __sincosf(r, &sc, &cc);
    g_cos[s * 64 + f] = cc;
    g_sin[s * 64 + f] = sc;
}

// -------------------- fused RMSNorm + RoPE (writes tf32-rounded) --------------------
__global__ __launch_bounds__(128) void norm_rope_kernel(float* __restrict__ Q,
                                                        float* __restrict__ Kb,
                                                        const float* __restrict__ qw,
                                                        const float* __restrict__ kw) {
    const int row = blockIdx.x;
    const int h   = blockIdx.y;
    const int d   = threadIdx.x;

    float* ptr;
    const float* w;
    if (h < NH) { ptr = Q  + (size_t)row * (NH  * HD) + h * HD;        w = qw; }
    else        { ptr = Kb + (size_t)row * (NKV * HD) + (h - NH) * HD; w = kw; }

    float v = ptr[d];
    float ss = v * v;
#pragma unroll
    for (int o = 16; o > 0; o >>= 1) ss += __shfl_xor_sync(0xffffffffu, ss, o);

    __shared__ float wsum[4];
    if ((d & 31) == 0) wsum[d >> 5] = ss;
    __syncthreads();
    float tot = wsum[0] + wsum[1] + wsum[2] + wsum[3];
    float rn  = rsqrtf(tot * (1.0f / 128.0f) + 1e-6f);
    float vn  = v * rn * w[d];

    __shared__ float sv[128];
    sv[d] = vn;
    __syncthreads();

    const int s = row & (SS - 1);
    const int i = d & 63;
    float c  = g_cos[s * 64 + i];
    float sn = g_sin[s * 64 + i];
    float t1 = sv[i];
    float t2 = sv[i + 64];
    float out = (d < 64) ? (t1 * c - t2 * sn) : (t1 * sn + t2 * c);
    ptr[d] = to_tf32(out);
}

// ==================== tensor-core flash attention ====================
#define QSTR 132
#define KSTR 132
#define VSTR 136
#define FL_SMEM ((128*QSTR + 2*64*KSTR + 2*64*VSTR) * 4)   // 204800 B

__global__ __launch_bounds__(256, 1) void flash_mma(const float* __restrict__ Q,
                                                    const float* __restrict__ K,
                                                    const float* __restrict__ V,
                                                    float* __restrict__ O) {
    extern __shared__ float sm[];
    float* Qs = sm;
    float* Ks = Qs + 128 * QSTR;
    float* Vs = Ks + 2 * 64 * KSTR;

    const int qi   = (int)gridDim.x - 1 - (int)blockIdx.x;
    const int h    = blockIdx.y;
    const int b    = blockIdx.z;
    const int kvh  = h >> 2;
    const int tid  = threadIdx.x;
    const int lane = tid & 31;
    const int w    = tid >> 5;
    const int g    = lane >> 2;
    const int tg   = lane & 3;
    const int qs   = qi * 128;
    const int ntiles = 2 * qi + 2;
    const float scl = 0.08838834764831845f * 1.4426950408889634f;

    const float* Qg = Q + (size_t)(b * SS + qs) * (NH * HD) + h * HD;
    const float* Kg = K + (size_t)(b * SS) * (NKV * HD) + kvh * HD;
    const float* Vg = V + (size_t)(b * SS) * (NKV * HD) + kvh * HD;

    for (int i = tid; i < 128 * 32; i += 256) {
        int r = i >> 5, c4 = i & 31;
        *(float4*)(Qs + r * QSTR + c4 * 4) =
            *(const float4*)(Qg + (size_t)r * (NH * HD) + c4 * 4);
    }

    for (int i = tid; i < 64 * 32; i += 256) {
        int r = i >> 5, c4 = i & 31;
        const float* kg = Kg + (size_t)r * (NKV * HD) + c4 * 4;
        const float* vg = Vg + (size_t)r * (NKV * HD) + c4 * 4;
        unsigned ka = (unsigned)__cvta_generic_to_shared(Ks + r * KSTR + c4 * 4);
        unsigned va = (unsigned)__cvta_generic_to_shared(Vs + r * VSTR + c4 * 4);
        CP_ASYNC16(ka, kg);
        CP_ASYNC16(va, vg);
    }
    CP_COMMIT();

    float m0 = -1e30f, m1 = -1e30f, l0 = 0.f, l1 = 0.f;
    float acc[16][4];
#pragma unroll
    for (int nt = 0; nt < 16; ++nt)
#pragma unroll
        for (int c = 0; c < 4; ++c) acc[nt][c] = 0.f;

    const int rowg0 = qs + w * 16 + g;
    const int rowg1 = rowg0 + 8;
    const int srcA  = (g << 2) | (tg >> 1);
    const int srcB  = srcA + 2;
    const bool odd  = (tg & 1);

    for (int kt = 0; kt < ntiles; ++kt) {
        __syncthreads();
        if (kt + 1 < ntiles) {
            int bf = (kt + 1) & 1;
            int ks0 = (kt + 1) * 64;
            float* Kw = Ks + bf * 64 * KSTR;
            float* Vw = Vs + bf * 64 * VSTR;
            for (int i = tid; i < 64 * 32; i += 256) {
                int r = i >> 5, c4 = i & 31;
                const float* kg = Kg + (size_t)(ks0 + r) * (NKV * HD) + c4 * 4;
                const float* vg = Vg + (size_t)(ks0 + r) * (NKV * HD) + c4 * 4;
                unsigned ka = (unsigned)__cvta_generic_to_shared(Kw + r * KSTR + c4 * 4);
                unsigned va = (unsigned)__cvta_generic_to_shared(Vw + r * VSTR + c4 * 4);
                CP_ASYNC16(ka, kg);
                CP_ASYNC16(va, vg);
            }
            CP_COMMIT();
            CP_WAIT1();
        } else {
            CP_WAIT0();
        }
        __syncthreads();

        const float* Kb = Ks + (kt & 1) * 64 * KSTR;
        const float* Vb = Vs + (kt & 1) * 64 * VSTR;

        float sacc[8][4];
#pragma unroll
        for (int nt = 0; nt < 8; ++nt)
#pragma unroll
            for (int c = 0; c < 4; ++c) sacc[nt][c] = 0.f;

#pragma unroll
        for (int ka = 0; ka < 16; ++ka) {
            const int k0 = ka * 8;
            const float* qp = Qs + (size_t)(w * 16 + g) * QSTR + k0 + tg;
            uint32_t a0 = __float_as_uint(qp[0]);
            uint32_t a1 = __float_as_uint(qp[8 * QSTR]);
            uint32_t a2 = __float_as_uint(qp[4]);
            uint32_t a3 = __float_as_uint(qp[8 * QSTR + 4]);
#pragma unroll
            for (int nt = 0; nt < 8; ++nt) {
                const float* kp = Kb + (size_t)(nt * 8 + g) * KSTR + k0 + tg;
                uint32_t b0 = __float_as_uint(kp[0]);
                uint32_t b1 = __float_as_uint(kp[4]);
                mma_tf32(sacc[nt][0], sacc[nt][1], sacc[nt][2], sacc[nt][3],
                         a0, a1, a2, a3, b0, b1);
            }
        }

        const bool need_mask = (kt >= 2 * qi);
        float mx0 = -1e30f, mx1 = -1e30f;
#pragma unroll
        for (int nt = 0; nt < 8; ++nt) {
            int c0 = kt * 64 + nt * 8 + 2 * tg;
            int c1 = c0 + 1;
            float v0 = sacc[nt][0] * scl, v1 = sacc[nt][1] * scl;
            float v2 = sacc[nt][2] * scl, v3 = sacc[nt][3] * scl;
            if (need_mask) {
                if (c0 > rowg0) v0 = -1e30f;
                if (c1 > rowg0) v1 = -1e30f;
                if (c0 > rowg1) v2 = -1e30f;
                if (c1 > rowg1) v3 = -1e30f;
            }
            sacc[nt][0] = v0; sacc[nt][1] = v1; sacc[nt][2] = v2; sacc[nt][3] = v3;
            mx0 = fmaxf(mx0, fmaxf(v0, v1));
            mx1 = fmaxf(mx1, fmaxf(v2, v3));
        }
        mx0 = fmaxf(mx0, __shfl_xor_sync(0xffffffffu, mx0, 1));
        mx0 = fmaxf(mx0, __shfl_xor_sync(0xffffffffu, mx0, 2));
        mx1 = fmaxf(mx1, __shfl_xor_sync(0xffffffffu, mx1, 1));
        mx1 = fmaxf(mx1, __shfl_xor_sync(0xffffffffu, mx1, 2));

        float mn0 = fmaxf(m0, mx0), mn1 = fmaxf(m1, mx1);
        float al0 = exp2f(m0 - mn0), al1 = exp2f(m1 - mn1);
        m0 = mn0; m1 = mn1;

        float ps0 = 0.f, ps1 = 0.f;
#pragma unroll
        for (int nt = 0; nt < 8; ++nt) {
            float p0 = exp2f(sacc[nt][0] - mn0);
            float p1 = exp2f(sacc[nt][1] - mn0);
            float p2 = exp2f(sacc[nt][2] - mn1);
            float p3 = exp2f(sacc[nt][3] - mn1);
            ps0 += p0 + p1; ps1 += p2 + p3;
            sacc[nt][0] = to_tf32(p0); sacc[nt][1] = to_tf32(p1);
            sacc[nt][2] = to_tf32(p2); sacc[nt][3] = to_tf32(p3);
        }
        ps0 += __shfl_xor_sync(0xffffffffu, ps0, 1);
        ps0 += __shfl_xor_sync(0xffffffffu, ps0, 2);
        ps1 += __shfl_xor_sync(0xffffffffu, ps1, 1);
        ps1 += __shfl_xor_sync(0xffffffffu, ps1, 2);
        l0 = l0 * al0 + ps0;
        l1 = l1 * al1 + ps1;

#pragma unroll
        for (int nt = 0; nt < 16; ++nt) {
            acc[nt][0] *= al0; acc[nt][1] *= al0;
            acc[nt][2] *= al1; acc[nt][3] *= al1;
        }

#pragma unroll
        for (int ka = 0; ka < 8; ++ka) {
            float e0 = __shfl_sync(0xffffffffu, sacc[ka][0], srcA);
            float e1 = __shfl_sync(0xffffffffu, sacc[ka][1], srcA);
            float e2 = __shfl_sync(0xffffffffu, sacc[ka][2], srcA);
            float e3 = __shfl_sync(0xffffffffu, sacc[ka][3], srcA);
            float f0 = __shfl_sync(0xffffffffu, sacc[ka][0], srcB);
            float f1 = __shfl_sync(0xffffffffu, sacc[ka][1], srcB);
            float f2 = __shfl_sync(0xffffffffu, sacc[ka][2], srcB);
            float f3 = __shfl_sync(0xffffffffu, sacc[ka][3], srcB);
            uint32_t pa0 = __float_as_uint(odd ? e1 : e0);
            uint32_t pa1 = __float_as_uint(odd ? e3 : e2);
            uint32_t pa2 = __float_as_uint(odd ? f1 : f0);
            uint32_t pa3 = __float_as_uint(odd ? f3 : f2);
            const int k0 = ka * 8;
#pragma unroll
            for (int nt = 0; nt < 16; ++nt) {
                const float* vp = Vb + (size_t)(k0 + tg) * VSTR + nt * 8 + g;
                uint32_t b0 = __float_as_uint(vp[0]);
                uint32_t b1 = __float_as_uint(vp[4 * VSTR]);
                mma_tf32(acc[nt][0], acc[nt][1], acc[nt][2], acc[nt][3],
                         pa0, pa1, pa2, pa3, b0, b1);
            }
        }
    }

    // epilogue: normalize + tf32-round (ctx feeds the pre-rounded GEMM)
    float inv0 = 1.0f / l0, inv1 = 1.0f / l1;
    float* Og = O + (size_t)(b * SS + qs + w * 16) * (NH * HD) + h * HD;
#pragma unroll
    for (int nt = 0; nt < 16; ++nt) {
        int col = nt * 8 + 2 * tg;
        float2 o0 = {to_tf32(acc[nt][0] * inv0), to_tf32(acc[nt][1] * inv0)};
        float2 o1 = {to_tf32(acc[nt][2] * inv1), to_tf32(acc[nt][3] * inv1)};
        *(float2*)(Og + (size_t)g * (NH * HD) + col)       = o0;
        *(float2*)(Og + (size_t)(g + 8) * (NH * HD) + col) = o1;
    }
}

// -------------------- launch --------------------
extern "C" void kernel_launch(void* const* d_in, const int* in_sizes, int n_in,
                              void* d_out, int out_size) {
    const float* x  = (const float*)d_in[0];
    const float* wq = (const float*)d_in[1];
    const float* wk = (const float*)d_in[2];
    const float* wv = (const float*)d_in[3];
    const float* wo = (const float*)d_in[4];
    const float* qw = (const float*)d_in[5];
    const float* kw = (const float*)d_in[6];
    float* out = (float*)d_out;

    float *qb, *kb, *vb, *ctx, *xr, *wt;
    cudaGetSymbolAddress((void**)&qb,  g_q);
    cudaGetSymbolAddress((void**)&kb,  g_k);
    cudaGetSymbolAddress((void**)&vb,  g_v);
    cudaGetSymbolAddress((void**)&ctx, g_ctx);
    cudaGetSymbolAddress((void**)&xr,  g_xr);
    cudaGetSymbolAddress((void**)&wt,  g_wt);

    cudaFuncSetAttribute(gemm_tf32, cudaFuncAttributeMaxDynamicSharedMemorySize, GEMM_SMEM);
    cudaFuncSetAttribute(flash_mma, cudaFuncAttributeMaxDynamicSharedMemorySize, FL_SMEM);

    // pre-rounded activations + rope tables
    round_copy<<<(MROWS * HH) / 4096, 1024>>>(x, xr);
    rope_table_kernel<<<64, 1024>>>();

    // QKV projections (weight rounded into reused scratch, then async GEMM)
    round_copy<<<(HH * 4096) / 4096, 1024>>>(wq, wt);
    gemm_tf32<<<dim3(32, 16), 256, GEMM_SMEM>>>(xr, wt, qb, MROWS, 4096, HH, 0);
    round_copy<<<(HH * 1024) / 4096, 1024>>>(wk, wt);
    gemm_tf32<<<dim3(8,  16), 256, GEMM_SMEM>>>(xr, wt, kb, MROWS, 1024, HH, 0);
    round_copy<<<(HH * 1024) / 4096, 1024>>>(wv, wt);
    gemm_tf32<<<dim3(8,  16), 256, GEMM_SMEM>>>(xr, wt, vb, MROWS, 1024, HH, 1);  // V rounded

    // RMSNorm + RoPE (tf32 out)
    norm_rope_kernel<<<dim3(MROWS, NH + NKV), 128>>>(qb, kb, qw, kw);

    // causal GQA attention on tensor cores
    flash_mma<<<dim3(SS / 128, NH, BB), 256, FL_SMEM>>>(qb, kb, vb, ctx);

    // output projection
    round_copy<<<(4096 * 4096) / 4096, 1024>>>(wo, wt);
    gemm_tf32<<<dim3(32, 16), 256, GEMM_SMEM>>>(ctx, wt, out, MROWS, 4096, 4096, 0);
}

// round 12
// speedup vs baseline: 1.6412x; 1.6412x over previous
#include <cuda_runtime.h>
#include <cuda_bf16.h>
#include <math.h>
#include <stdint.h>

// Problem constants
#define BB   2
#define SS   1024
#define HH   4096
#define NH   32
#define NKV  8
#define HD   128
#define MROWS (BB*SS)          // 2048
#define QKVN (NH*HD + 2*NKV*HD)   // 6144 fused QKV width
#define KOFF (NH*HD)              // 4096
#define VOFF (NH*HD + NKV*HD)     // 5120

// -------------------- scratch (device globals; no allocation) --------------------
__device__ float g_qkv[MROWS * QKVN];       // 2048 x 6144 fused Q|K|V
__device__ float g_ctx[MROWS * NH * HD];    // 2048 x 4096
__device__ float g_xr [MROWS * HH];         // tf32-rounded x
__device__ float g_wt [HH * QKVN];          // tf32-rounded fused weight scratch
__device__ float g_cos[SS * (HD/2)];
__device__ float g_sin[SS * (HD/2)];

__device__ __forceinline__ float to_tf32(float x) {
    float r;
    asm("cvt.rna.tf32.f32 %0, %1;" : "=f"(r) : "f"(x));
    return r;
}

__device__ __forceinline__ void mma_tf32(float& d0, float& d1, float& d2, float& d3,
                                         uint32_t a0, uint32_t a1, uint32_t a2, uint32_t a3,
                                         uint32_t b0, uint32_t b1) {
    asm volatile("mma.sync.aligned.m16n8k8.row.col.f32.tf32.tf32.f32 "
                 "{%0,%1,%2,%3},{%4,%5,%6,%7},{%8,%9},{%0,%1,%2,%3};"
                 : "+f"(d0), "+f"(d1), "+f"(d2), "+f"(d3)
                 : "r"(a0), "r"(a1), "r"(a2), "r"(a3), "r"(b0), "r"(b1));
}

#define CP_ASYNC16(saddr, gptr) \
    asm volatile("cp.async.cg.shared.global [%0], [%1], 16;" :: "r"(saddr), "l"(gptr))
#define CP_COMMIT() asm volatile("cp.async.commit_group;")
#define CP_WAIT1()  asm volatile("cp.async.wait_group 1;")
#define CP_WAIT0()  asm volatile("cp.async.wait_group 0;")

// ==================== TF32 tensor-core GEMM (cp.async 3-stage, 2 CTA/SM) ============
// C[M,N] = A[M,K] @ B[K,N], row-major, inputs ALREADY tf32-rounded.
// 128x128 block, BK=32, 256 threads (8 warps), warp tile 64x32.
// 3-stage cp.async ring, one barrier per K-iter, 107.5KB smem -> 2 CTAs/SM.

#define ASTRIDE 36    // floats; conflict-free frag LDS
#define BSTRIDE 136
#define STG_FLOATS (128*ASTRIDE + 32*BSTRIDE)     // 8960 floats = 35840 B
#define NSTG 3
#define GEMM_SMEM (NSTG * STG_FLOATS * 4)         // 107520 B

__device__ __forceinline__ void stage_tile(int tid, float* smbase,
                                           const float* __restrict__ Ag,
                                           const float* __restrict__ Bg,
                                           int N, int K, int t) {
    float* As = smbase + (t % 3) * STG_FLOATS;
    float* Bs = As + 128 * ASTRIDE;
    const float* ag = Ag + t * 32;
    const float* bg = Bg + (size_t)(t * 32) * N;
#pragma unroll
    for (int i = 0; i < 4; ++i) {
        int e = tid + i * 256;
        int r = e >> 3, c = e & 7;          // A: 128 rows x 8 chunks
        unsigned d = (unsigned)__cvta_generic_to_shared(As + r * ASTRIDE + c * 4);
        CP_ASYNC16(d, ag + (size_t)r * K + c * 4);
    }
#pragma unroll
    for (int i = 0; i < 4; ++i) {
        int e = tid + i * 256;
        int r = e >> 5, c = e & 31;         // B: 32 rows x 32 chunks
        unsigned d = (unsigned)__cvta_generic_to_shared(Bs + r * BSTRIDE + c * 4);
        CP_ASYNC16(d, bg + (size_t)r * N + c * 4);
    }
    CP_COMMIT();
}

__global__ __launch_bounds__(256, 2) void gemm_tf32(const float* __restrict__ A,
                                                    const float* __restrict__ B,
                                                    float* __restrict__ C,
                                                    int M, int N, int K, int rthresh) {
    extern __shared__ float sm[];

    const int tid  = threadIdx.x;
    const int lane = tid & 31;
    const int w    = tid >> 5;
    const int g    = lane >> 2;
    const int tg   = lane & 3;
    const int wm   = (w & 1) * 64;
    const int wn   = (w >> 1) * 32;
    const int bm   = blockIdx.y * 128;
    const int bn   = blockIdx.x * 128;

    const float* Ag = A + (size_t)bm * K;
    const float* Bg = B + bn;
    const int T = K >> 5;

    stage_tile(tid, sm, Ag, Bg, N, K, 0);
    stage_tile(tid, sm, Ag, Bg, N, K, 1);

    float acc[4][4][4];
#pragma unroll
    for (int mi = 0; mi < 4; ++mi)
#pragma unroll
        for (int ni = 0; ni < 4; ++ni)
#pragma unroll
            for (int c = 0; c < 4; ++c) acc[mi][ni][c] = 0.f;

    for (int t = 0; t < T; ++t) {
        if (t < T - 1) CP_WAIT1();   // groups outstanding: {t, t+1} -> t done
        else           CP_WAIT0();   // only {t} outstanding
        __syncthreads();             // t visible to all; compute(t-1) done everywhere
        if (t + 2 < T) stage_tile(tid, sm, Ag, Bg, N, K, t + 2);   // buf (t-1)%3, free

        const float* Ab = sm + (t % 3) * STG_FLOATS;
        const float* Bb = Ab + 128 * ASTRIDE;

#pragma unroll
        for (int ka = 0; ka < 4; ++ka) {
            const int k0 = ka * 8;
            uint32_t af[4][4], bf[4][2];
#pragma unroll
            for (int mi = 0; mi < 4; ++mi) {
                const float* p = Ab + (size_t)(wm + mi * 16 + g) * ASTRIDE + k0 + tg;
                af[mi][0] = __float_as_uint(p[0]);
                af[mi][1] = __float_as_uint(p[8 * ASTRIDE]);
                af[mi][2] = __float_as_uint(p[4]);
                af[mi][3] = __float_as_uint(p[8 * ASTRIDE + 4]);
            }
#pragma unroll
            for (int ni = 0; ni < 4; ++ni) {
                const float* p = Bb + (size_t)(k0 + tg) * BSTRIDE + wn + ni * 8 + g;
                bf[ni][0] = __float_as_uint(p[0]);
                bf[ni][1] = __float_as_uint(p[4 * BSTRIDE]);
            }
#pragma unroll
            for (int mi = 0; mi < 4; ++mi)
#pragma unroll
                for (int ni = 0; ni < 4; ++ni)
                    mma_tf32(acc[mi][ni][0], acc[mi][ni][1], acc[mi][ni][2], acc[mi][ni][3],
                             af[mi][0], af[mi][1], af[mi][2], af[mi][3],
                             bf[ni][0], bf[ni][1]);
        }
    }

    // ---- epilogue: tf32-round columns >= rthresh (V block feeds flash directly)
#pragma unroll
    for (int mi = 0; mi < 4; ++mi) {
        int r0 = bm + wm + mi * 16 + g;
#pragma unroll
        for (int ni = 0; ni < 4; ++ni) {
            int c0 = bn + wn + ni * 8 + 2 * tg;
            float o0 = acc[mi][ni][0], o1 = acc[mi][ni][1];
            float o2 = acc[mi][ni][2], o3 = acc[mi][ni][3];
            if (c0 >= rthresh) {
                o0 = to_tf32(o0); o1 = to_tf32(o1);
                o2 = to_tf32(o2); o3 = to_tf32(o3);
            }
            float2 v0 = {o0, o1};
            float2 v1 = {o2, o3};
            *(float2*)(C + (size_t)r0 * N + c0)       = v0;
            *(float2*)(C + (size_t)(r0 + 8) * N + c0) = v1;
        }
    }
}

// -------------------- tf32-rounded copies --------------------
__global__ void round_copy(const float* __restrict__ in, float* __restrict__ outp) {
    int i = blockIdx.x * 1024 + threadIdx.x;
    float4 v = ((const float4*)in)[i];
    v.x = to_tf32(v.x); v.y = to_tf32(v.y);
    v.z = to_tf32(v.z); v.w = to_tf32(v.w);
    ((float4*)outp)[i] = v;
}

// copy [K, Nw] row-major into out rows of stride Nout at column offset off
__global__ void round_copy_strided(const float* __restrict__ in, float* __restrict__ outp,
                                   int Nw4, int Nout, int off) {
    int i = blockIdx.x * 256 + threadIdx.x;          // float4 index
    int r = i / Nw4, c = i - r * Nw4;
    float4 v = ((const float4*)in)[i];
    v.x = to_tf32(v.x); v.y = to_tf32(v.y);
    v.z = to_tf32(v.z); v.w = to_tf32(v.w);
    *(float4*)(outp + (size_t)r * Nout + off + c * 4) = v;
}

// -------------------- RoPE cos/sin table --------------------
__global__ __launch_bounds__(1024) void rope_table_kernel() {
    __shared__ double sinv[64];
    const int tid = threadIdx.x;
    if (tid < 64) sinv[tid] = exp(-(double)tid / 64.0 * log(10000.0));
    __syncthreads();
    const int f = tid & 63;
    const int s = blockIdx.x * 16 + (tid >> 6);
    double a = (double)s * sinv[f];
    double q = rint(a * 0.15915494309189535);      // 1/(2*pi)
    float r = (float)(a - q * 6.283185307179586);  // in [-pi, pi]
    float sc, cc;
    __sincosf(r, &sc, &cc);
    g_cos[s * 64 + f] = cc;
    g_sin[s * 64 + f] = sc;
}

// -------------------- fused RMSNorm + RoPE on fused QKV buffer --------------------
__global__ __launch_bounds__(128) void norm_rope_kernel(float* __restrict__ QKV,
                                                        const float* __restrict__ qw,
                                                        const float* __restrict__ kw) {
    const int row = blockIdx.x;       // 0..2047
    const int h   = blockIdx.y;       // 0..39 (0-31 Q heads, 32-39 K heads)
    const int d   = threadIdx.x;

    float* ptr;
    const float* w;
    if (h < NH) { ptr = QKV + (size_t)row * QKVN + h * HD;               w = qw; }
    else        { ptr = QKV + (size_t)row * QKVN + KOFF + (h - NH) * HD; w = kw; }

    float v = ptr[d];
    float ss = v * v;
#pragma unroll
    for (int o = 16; o > 0; o >>= 1) ss += __shfl_xor_sync(0xffffffffu, ss, o);

    __shared__ float wsum[4];
    if ((d & 31) == 0) wsum[d >> 5] = ss;
    __syncthreads();
    float tot = wsum[0] + wsum[1] + wsum[2] + wsum[3];
    float rn  = rsqrtf(tot * (1.0f / 128.0f) + 1e-6f);
    float vn  = v * rn * w[d];

    __shared__ float sv[128];
    sv[d] = vn;
    __syncthreads();

    const int s = row & (SS - 1);
    const int i = d & 63;
    float c  = g_cos[s * 64 + i];
    float sn = g_sin[s * 64 + i];
    float t1 = sv[i];
    float t2 = sv[i + 64];
    float out = (d < 64) ? (t1 * c - t2 * sn) : (t1 * sn + t2 * c);
    ptr[d] = to_tf32(out);
}

// ==================== tensor-core flash attention ====================
#define QSTR 132
#define KSTR 132
#define VSTR 136
#define FL_SMEM ((128*QSTR + 2*64*KSTR + 2*64*VSTR) * 4)   // 204800 B

__global__ __launch_bounds__(256, 1) void flash_mma(const float* __restrict__ QKV,
                                                    float* __restrict__ O) {
    extern __shared__ float sm[];
    float* Qs = sm;
    float* Ks = Qs + 128 * QSTR;
    float* Vs = Ks + 2 * 64 * KSTR;

    const int qi   = (int)gridDim.x - 1 - (int)blockIdx.x;
    const int h    = blockIdx.y;
    const int b    = blockIdx.z;
    const int kvh  = h >> 2;
    const int tid  = threadIdx.x;
    const int lane = tid & 31;
    const int w    = tid >> 5;
    const int g    = lane >> 2;
    const int tg   = lane & 3;
    const int qs   = qi * 128;
    const int ntiles = 2 * qi + 2;
    const float scl = 0.08838834764831845f * 1.4426950408889634f;

    const float* Qg = QKV + (size_t)(b * SS + qs) * QKVN + h * HD;
    const float* Kg = QKV + (size_t)(b * SS) * QKVN + KOFF + kvh * HD;
    const float* Vg = QKV + (size_t)(b * SS) * QKVN + VOFF + kvh * HD;

    for (int i = tid; i < 128 * 32; i += 256) {
        int r = i >> 5, c4 = i & 31;
        *(float4*)(Qs + r * QSTR + c4 * 4) =
            *(const float4*)(Qg + (size_t)r * QKVN + c4 * 4);
    }

    for (int i = tid; i < 64 * 32; i += 256) {
        int r = i >> 5, c4 = i & 31;
        const float* kg = Kg + (size_t)r * QKVN + c4 * 4;
        const float* vg = Vg + (size_t)r * QKVN + c4 * 4;
        unsigned ka = (unsigned)__cvta_generic_to_shared(Ks + r * KSTR + c4 * 4);
        unsigned va = (unsigned)__cvta_generic_to_shared(Vs + r * VSTR + c4 * 4);
        CP_ASYNC16(ka, kg);
        CP_ASYNC16(va, vg);
    }
    CP_COMMIT();

    float m0 = -1e30f, m1 = -1e30f, l0 = 0.f, l1 = 0.f;
    float acc[16][4];
#pragma unroll
    for (int nt = 0; nt < 16; ++nt)
#pragma unroll
        for (int c = 0; c < 4; ++c) acc[nt][c] = 0.f;

    const int rowg0 = qs + w * 16 + g;
    const int rowg1 = rowg0 + 8;
    const int srcA  = (g << 2) | (tg >> 1);
    const int srcB  = srcA + 2;
    const bool odd  = (tg & 1);

    for (int kt = 0; kt < ntiles; ++kt) {
        __syncthreads();
        if (kt + 1 < ntiles) {
            int bf = (kt + 1) & 1;
            int ks0 = (kt + 1) * 64;
            float* Kw = Ks + bf * 64 * KSTR;
            float* Vw = Vs + bf * 64 * VSTR;
            for (int i = tid; i < 64 * 32; i += 256) {
                int r = i >> 5, c4 = i & 31;
                const float* kg = Kg + (size_t)(ks0 + r) * QKVN + c4 * 4;
                const float* vg = Vg + (size_t)(ks0 + r) * QKVN + c4 * 4;
                unsigned ka = (unsigned)__cvta_generic_to_shared(Kw + r * KSTR + c4 * 4);
                unsigned va = (unsigned)__cvta_generic_to_shared(Vw + r * VSTR + c4 * 4);
                CP_ASYNC16(ka, kg);
                CP_ASYNC16(va, vg);
            }
            CP_COMMIT();
            CP_WAIT1();
        } else {
            CP_WAIT0();
        }
        __syncthreads();

        const float* Kb = Ks + (kt & 1) * 64 * KSTR;
        const float* Vb = Vs + (kt & 1) * 64 * VSTR;

        float sacc[8][4];
#pragma unroll
        for (int nt = 0; nt < 8; ++nt)
#pragma unroll
            for (int c = 0; c < 4; ++c) sacc[nt][c] = 0.f;

#pragma unroll
        for (int ka = 0; ka < 16; ++ka) {
            const int k0 = ka * 8;
            const float* qp = Qs + (size_t)(w * 16 + g) * QSTR + k0 + tg;
            uint32_t a0 = __float_as_uint(qp[0]);
            uint32_t a1 = __float_as_uint(qp[8 * QSTR]);
            uint32_t a2 = __float_as_uint(qp[4]);
            uint32_t a3 = __float_as_uint(qp[8 * QSTR + 4]);
#pragma unroll
            for (int nt = 0; nt < 8; ++nt) {
                const float* kp = Kb + (size_t)(nt * 8 + g) * KSTR + k0 + tg;
                uint32_t b0 = __float_as_uint(kp[0]);
                uint32_t b1 = __float_as_uint(kp[4]);
                mma_tf32(sacc[nt][0], sacc[nt][1], sacc[nt][2], sacc[nt][3],
                         a0, a1, a2, a3, b0, b1);
            }
        }

        const bool need_mask = (kt >= 2 * qi);
        float mx0 = -1e30f, mx1 = -1e30f;
#pragma unroll
        for (int nt = 0; nt < 8; ++nt) {
            int c0 = kt * 64 + nt * 8 + 2 * tg;
            int c1 = c0 + 1;
            float v0 = sacc[nt][0] * scl, v1 = sacc[nt][1] * scl;
            float v2 = sacc[nt][2] * scl, v3 = sacc[nt][3] * scl;
            if (need_mask) {
                if (c0 > rowg0) v0 = -1e30f;
                if (c1 > rowg0) v1 = -1e30f;
                if (c0 > rowg1) v2 = -1e30f;
                if (c1 > rowg1) v3 = -1e30f;
            }
            sacc[nt][0] = v0; sacc[nt][1] = v1; sacc[nt][2] = v2; sacc[nt][3] = v3;
            mx0 = fmaxf(mx0, fmaxf(v0, v1));
            mx1 = fmaxf(mx1, fmaxf(v2, v3));
        }
        mx0 = fmaxf(mx0, __shfl_xor_sync(0xffffffffu, mx0, 1));
        mx0 = fmaxf(mx0, __shfl_xor_sync(0xffffffffu, mx0, 2));
        mx1 = fmaxf(mx1, __shfl_xor_sync(0xffffffffu, mx1, 1));
        mx1 = fmaxf(mx1, __shfl_xor_sync(0xffffffffu, mx1, 2));

        float mn0 = fmaxf(m0, mx0), mn1 = fmaxf(m1, mx1);
        float al0 = exp2f(m0 - mn0), al1 = exp2f(m1 - mn1);
        m0 = mn0; m1 = mn1;

        float ps0 = 0.f, ps1 = 0.f;
#pragma unroll
        for (int nt = 0; nt < 8; ++nt) {
            float p0 = exp2f(sacc[nt][0] - mn0);
            float p1 = exp2f(sacc[nt][1] - mn0);
            float p2 = exp2f(sacc[nt][2] - mn1);
            float p3 = exp2f(sacc[nt][3] - mn1);
            ps0 += p0 + p1; ps1 += p2 + p3;
            sacc[nt][0] = to_tf32(p0); sacc[nt][1] = to_tf32(p1);
            sacc[nt][2] = to_tf32(p2); sacc[nt][3] = to_tf32(p3);
        }
        ps0 += __shfl_xor_sync(0xffffffffu, ps0, 1);
        ps0 += __shfl_xor_sync(0xffffffffu, ps0, 2);
        ps1 += __shfl_xor_sync(0xffffffffu, ps1, 1);
        ps1 += __shfl_xor_sync(0xffffffffu, ps1, 2);
        l0 = l0 * al0 + ps0;
        l1 = l1 * al1 + ps1;

#pragma unroll
        for (int nt = 0; nt < 16; ++nt) {
            acc[nt][0] *= al0; acc[nt][1] *= al0;
            acc[nt][2] *= al1; acc[nt][3] *= al1;
        }

#pragma unroll
        for (int ka = 0; ka < 8; ++ka) {
            float e0 = __shfl_sync(0xffffffffu, sacc[ka][0], srcA);
            float e1 = __shfl_sync(0xffffffffu, sacc[ka][1], srcA);
            float e2 = __shfl_sync(0xffffffffu, sacc[ka][2], srcA);
            float e3 = __shfl_sync(0xffffffffu, sacc[ka][3], srcA);
            float f0 = __shfl_sync(0xffffffffu, sacc[ka][0], srcB);
            float f1 = __shfl_sync(0xffffffffu, sacc[ka][1], srcB);
            float f2 = __shfl_sync(0xffffffffu, sacc[ka][2], srcB);
            float f3 = __shfl_sync(0xffffffffu, sacc[ka][3], srcB);
            uint32_t pa0 = __float_as_uint(odd ? e1 : e0);
            uint32_t pa1 = __float_as_uint(odd ? e3 : e2);
            uint32_t pa2 = __float_as_uint(odd ? f1 : f0);
            uint32_t pa3 = __float_as_uint(odd ? f3 : f2);
            const int k0 = ka * 8;
#pragma unroll
            for (int nt = 0; nt < 16; ++nt) {
                const float* vp = Vb + (size_t)(k0 + tg) * VSTR + nt * 8 + g;
                uint32_t b0 = __float_as_uint(vp[0]);
                uint32_t b1 = __float_as_uint(vp[4 * VSTR]);
                mma_tf32(acc[nt][0], acc[nt][1], acc[nt][2], acc[nt][3],
                         pa0, pa1, pa2, pa3, b0, b1);
            }
        }
    }

    // epilogue: normalize + tf32-round (ctx feeds the pre-rounded GEMM)
    float inv0 = 1.0f / l0, inv1 = 1.0f / l1;
    float* Og = O + (size_t)(b * SS + qs + w * 16) * (NH * HD) + h * HD;
#pragma unroll
    for (int nt = 0; nt < 16; ++nt) {
        int col = nt * 8 + 2 * tg;
        float2 o0 = {to_tf32(acc[nt][0] * inv0), to_tf32(acc[nt][1] * inv0)};
        float2 o1 = {to_tf32(acc[nt][2] * inv1), to_tf32(acc[nt][3] * inv1)};
        *(float2*)(Og + (size_t)g * (NH * HD) + col)       = o0;
        *(float2*)(Og + (size_t)(g + 8) * (NH * HD) + col) = o1;
    }
}

// -------------------- launch --------------------
extern "C" void kernel_launch(void* const* d_in, const int* in_sizes, int n_in,
                              void* d_out, int out_size) {
    const float* x  = (const float*)d_in[0];
    const float* wq = (const float*)d_in[1];
    const float* wk = (const float*)d_in[2];
    const float* wv = (const float*)d_in[3];
    const float* wo = (const float*)d_in[4];
    const float* qw = (const float*)d_in[5];
    const float* kw = (const float*)d_in[6];
    float* out = (float*)d_out;

    float *qkv, *ctx, *xr, *wt;
    cudaGetSymbolAddress((void**)&qkv, g_qkv);
    cudaGetSymbolAddress((void**)&ctx, g_ctx);
    cudaGetSymbolAddress((void**)&xr,  g_xr);
    cudaGetSymbolAddress((void**)&wt,  g_wt);

    cudaFuncSetAttribute(gemm_tf32, cudaFuncAttributeMaxDynamicSharedMemorySize, GEMM_SMEM);
    cudaFuncSetAttribute(flash_mma, cudaFuncAttributeMaxDynamicSharedMemorySize, FL_SMEM);

    // pre-rounded activations + rope tables
    round_copy<<<(MROWS * HH) / 4096, 1024>>>(x, xr);
    rope_table_kernel<<<64, 1024>>>();

    // fused QKV weight concat (rounded): wt[K=4096, N=6144] = [wq | wk | wv]
    round_copy_strided<<<(HH * 4096) / 1024, 256>>>(wq, wt, 4096 / 4, QKVN, 0);
    round_copy_strided<<<(HH * 1024) / 1024, 256>>>(wk, wt, 1024 / 4, QKVN, KOFF);
    round_copy_strided<<<(HH * 1024) / 1024, 256>>>(wv, wt, 1024 / 4, QKVN, VOFF);

    // fused QKV projection; round V columns (>= VOFF) in epilogue
    gemm_tf32<<<dim3(QKVN / 128, 16), 256, GEMM_SMEM>>>(xr, wt, qkv, MROWS, QKVN, HH, VOFF);

    // RMSNorm + RoPE (tf32 out) on Q and K inside the fused buffer
    norm_rope_kernel<<<dim3(MROWS, NH + NKV), 128>>>(qkv, qw, kw);

    // causal GQA attention on tensor cores
    flash_mma<<<dim3(SS / 128, NH, BB), 256, FL_SMEM>>>(qkv, ctx);

    // output projection
    round_copy<<<(4096 * 4096) / 4096, 1024>>>(wo, wt);
    gemm_tf32<<<dim3(32, 16), 256, GEMM_SMEM>>>(ctx, wt, out, MROWS, 4096, 4096, 1 << 30);
}

// round 13
// speedup vs baseline: 2.5379x; 1.5464x over previous
#include <cuda_runtime.h>
#include <cuda_fp16.h>
#include <math.h>
#include <stdint.h>

// Problem constants
#define BB   2
#define SS   1024
#define HH   4096
#define NH   32
#define NKV  8
#define HD   128
#define MROWS (BB*SS)          // 2048
#define QKVN (NH*HD + 2*NKV*HD)   // 6144 fused QKV width
#define KOFF (NH*HD)              // 4096
#define VOFF (NH*HD + NKV*HD)     // 5120

// -------------------- scratch (device globals; no allocation) --------------------
__device__ float    g_qkv[MROWS * QKVN];        // 2048 x 6144 fused Q|K|V (fp32)
__device__ __half   g_ctx[MROWS * NH * HD];     // 2048 x 4096 (fp16, feeds wo GEMM)
__device__ __half   g_xh [MROWS * HH];          // fp16 x
__device__ uint32_t g_wp [(HH/2) * QKVN];       // packed {k,k+1} half2 weights (reused)
__device__ float    g_cos[SS * (HD/2)];
__device__ float    g_sin[SS * (HD/2)];

__device__ __forceinline__ float to_tf32(float x) {
    float r;
    asm("cvt.rna.tf32.f32 %0, %1;" : "=f"(r) : "f"(x));
    return r;
}

// fp16 tensor-core mma: D(16x8,f32) += A(16x16,f16) * B(16x8,f16)
__device__ __forceinline__ void mma_f16(float& d0, float& d1, float& d2, float& d3,
                                        uint32_t a0, uint32_t a1, uint32_t a2, uint32_t a3,
                                        uint32_t b0, uint32_t b1) {
    asm volatile("mma.sync.aligned.m16n8k16.row.col.f32.f16.f16.f32 "
                 "{%0,%1,%2,%3},{%4,%5,%6,%7},{%8,%9},{%0,%1,%2,%3};"
                 : "+f"(d0), "+f"(d1), "+f"(d2), "+f"(d3)
                 : "r"(a0), "r"(a1), "r"(a2), "r"(a3), "r"(b0), "r"(b1));
}

// tf32 mma (flash kernel)
__device__ __forceinline__ void mma_tf32(float& d0, float& d1, float& d2, float& d3,
                                         uint32_t a0, uint32_t a1, uint32_t a2, uint32_t a3,
                                         uint32_t b0, uint32_t b1) {
    asm volatile("mma.sync.aligned.m16n8k8.row.col.f32.tf32.tf32.f32 "
                 "{%0,%1,%2,%3},{%4,%5,%6,%7},{%8,%9},{%0,%1,%2,%3};"
                 : "+f"(d0), "+f"(d1), "+f"(d2), "+f"(d3)
                 : "r"(a0), "r"(a1), "r"(a2), "r"(a3), "r"(b0), "r"(b1));
}

#define CP_ASYNC16(saddr, gptr) \
    asm volatile("cp.async.cg.shared.global [%0], [%1], 16;" :: "r"(saddr), "l"(gptr))
#define CP_COMMIT() asm volatile("cp.async.commit_group;")
#define CP_WAIT1()  asm volatile("cp.async.wait_group 1;")
#define CP_WAIT0()  asm volatile("cp.async.wait_group 0;")

// ==================== FP16 tensor-core GEMM (cp.async 3-stage, 2 CTA/SM) ============
// C[M,N](f32) = A[M,K](f16 row-major) @ B(packed {k,k+1} half2 words [K/2][N]).
// 128x128 block, BK=32, 256 threads (8 warps), warp tile 64x32, mma.m16n8k16.
// A smem: 128 rows x 20 u32 (16 data words + pad)  -> banks g*20+tg distinct.
// B smem: 16 kp-rows x 136 u32 (128 data + pad)    -> banks tg*8+g distinct.

#define ASTW 20
#define BSTW 136
#define STGW (128*ASTW + 16*BSTW)          // 4736 u32 = 18944 B
#define NSTG 3
#define GEMM_SMEM (NSTG * STGW * 4)        // 56832 B

__device__ __forceinline__ void stage_tile(int tid, uint32_t* smbase,
                                           const __half* __restrict__ Ag,
                                           const uint32_t* __restrict__ Bg,
                                           int N, int K, int t) {
    uint32_t* As = smbase + (t % 3) * STGW;
    uint32_t* Bs = As + 128 * ASTW;
#pragma unroll
    for (int i = 0; i < 2; ++i) {
        int e = tid + i * 256;
        int r = e >> 2, c = e & 3;          // A: 128 rows x 4 chunks of 16B
        unsigned d = (unsigned)__cvta_generic_to_shared(As + r * ASTW + c * 4);
        CP_ASYNC16(d, Ag + (size_t)r * K + t * 32 + c * 8);
    }
#pragma unroll
    for (int i = 0; i < 2; ++i) {
        int e = tid + i * 256;
        int r = e >> 5, c = e & 31;         // B: 16 kp-rows x 32 chunks of 16B
        unsigned d = (unsigned)__cvta_generic_to_shared(Bs + r * BSTW + c * 4);
        CP_ASYNC16(d, Bg + (size_t)(t * 16 + r) * N + c * 4);
    }
    CP_COMMIT();
}

__global__ __launch_bounds__(256, 2) void gemm_f16(const __half* __restrict__ A,
                                                   const uint32_t* __restrict__ Bp,
                                                   float* __restrict__ C,
                                                   int M, int N, int K, int rthresh) {
    extern __shared__ uint32_t smw[];

    const int tid  = threadIdx.x;
    const int lane = tid & 31;
    const int w    = tid >> 5;
    const int g    = lane >> 2;
    const int tg   = lane & 3;
    const int wm   = (w & 1) * 64;
    const int wn   = (w >> 1) * 32;
    const int bm   = blockIdx.y * 128;
    const int bn   = blockIdx.x * 128;

    const __half*   Ag = A  + (size_t)bm * K;
    const uint32_t* Bg = Bp + bn;
    const int T = K >> 5;

    stage_tile(tid, smw, Ag, Bg, N, K, 0);
    stage_tile(tid, smw, Ag, Bg, N, K, 1);

    float acc[4][4][4];
#pragma unroll
    for (int mi = 0; mi < 4; ++mi)
#pragma unroll
        for (int ni = 0; ni < 4; ++ni)
#pragma unroll
            for (int c = 0; c < 4; ++c) acc[mi][ni][c] = 0.f;

    for (int t = 0; t < T; ++t) {
        if (t < T - 1) CP_WAIT1();
        else           CP_WAIT0();
        __syncthreads();
        if (t + 2 < T) stage_tile(tid, smw, Ag, Bg, N, K, t + 2);

        const uint32_t* Ab = smw + (t % 3) * STGW;
        const uint32_t* Bb = Ab + 128 * ASTW;

#pragma unroll
        for (int ks = 0; ks < 2; ++ks) {
            const int k0w = ks * 8;
            uint32_t af[4][4], bf[4][2];
#pragma unroll
            for (int mi = 0; mi < 4; ++mi) {
                const uint32_t* p = Ab + (size_t)(wm + mi * 16 + g) * ASTW + k0w + tg;
                af[mi][0] = p[0];
                af[mi][1] = p[8 * ASTW];
                af[mi][2] = p[4];
                af[mi][3] = p[8 * ASTW + 4];
            }
#pragma unroll
            for (int ni = 0; ni < 4; ++ni) {
                const uint32_t* p = Bb + (size_t)(k0w + tg) * BSTW + wn + ni * 8 + g;
                bf[ni][0] = p[0];
                bf[ni][1] = p[4 * BSTW];
            }
#pragma unroll
            for (int mi = 0; mi < 4; ++mi)
#pragma unroll
                for (int ni = 0; ni < 4; ++ni)
                    mma_f16(acc[mi][ni][0], acc[mi][ni][1], acc[mi][ni][2], acc[mi][ni][3],
                            af[mi][0], af[mi][1], af[mi][2], af[mi][3],
                            bf[ni][0], bf[ni][1]);
        }
    }

    // ---- epilogue: tf32-round columns >= rthresh (V block feeds tf32 flash)
#pragma unroll
    for (int mi = 0; mi < 4; ++mi) {
        int r0 = bm + wm + mi * 16 + g;
#pragma unroll
        for (int ni = 0; ni < 4; ++ni) {
            int c0 = bn + wn + ni * 8 + 2 * tg;
            float o0 = acc[mi][ni][0], o1 = acc[mi][ni][1];
            float o2 = acc[mi][ni][2], o3 = acc[mi][ni][3];
            if (c0 >= rthresh) {
                o0 = to_tf32(o0); o1 = to_tf32(o1);
                o2 = to_tf32(o2); o3 = to_tf32(o3);
            }
            float2 v0 = {o0, o1};
            float2 v1 = {o2, o3};
            *(float2*)(C + (size_t)r0 * N + c0)       = v0;
            *(float2*)(C + (size_t)(r0 + 8) * N + c0) = v1;
        }
    }
}

// -------------------- x -> fp16 copy --------------------
__global__ void pack_x(const float* __restrict__ in, __half* __restrict__ outp) {
    int i = blockIdx.x * 256 + threadIdx.x;     // float4 index
    float4 v = ((const float4*)in)[i];
    __half2 h0 = __floats2half2_rn(v.x, v.y);
    __half2 h1 = __floats2half2_rn(v.z, v.w);
    uint2 u = {*(uint32_t*)&h0, *(uint32_t*)&h1};
    ((uint2*)outp)[i] = u;
}

// -------------------- weight -> packed {k,k+1} half2 words --------------------
// in: [K][Nw] f32 row-major. out word (kp, n) = {in[2kp][n], in[2kp+1][n]},
// written at column offset `off` in rows of stride Nout.
__global__ void pack_weight(const float* __restrict__ in, uint32_t* __restrict__ outp,
                            int Nw4, int Nw, int Nout, int off) {
    int i = blockIdx.x * 256 + threadIdx.x;     // (kp, 4-col group) index
    int kp = i / Nw4, c = i - kp * Nw4;
    float4 r0 = *(const float4*)(in + (size_t)(2 * kp)     * Nw + c * 4);
    float4 r1 = *(const float4*)(in + (size_t)(2 * kp + 1) * Nw + c * 4);
    __half2 h0 = __floats2half2_rn(r0.x, r1.x);
    __half2 h1 = __floats2half2_rn(r0.y, r1.y);
    __half2 h2 = __floats2half2_rn(r0.z, r1.z);
    __half2 h3 = __floats2half2_rn(r0.w, r1.w);
    uint4 u = {*(uint32_t*)&h0, *(uint32_t*)&h1, *(uint32_t*)&h2, *(uint32_t*)&h3};
    *(uint4*)(outp + (size_t)kp * Nout + off + c * 4) = u;
}

// -------------------- RoPE cos/sin table --------------------
__global__ __launch_bounds__(1024) void rope_table_kernel() {
    __shared__ double sinv[64];
    const int tid = threadIdx.x;
    if (tid < 64) sinv[tid] = exp(-(double)tid / 64.0 * log(10000.0));
    __syncthreads();
    const int f = tid & 63;
    const int s = blockIdx.x * 16 + (tid >> 6);
    double a = (double)s * sinv[f];
    double q = rint(a * 0.15915494309189535);
    float r = (float)(a - q * 6.283185307179586);
    float sc, cc;
    __sincosf(r, &sc, &cc);
    g_cos[s * 64 + f] = cc;
    g_sin[s * 64 + f] = sc;
}

// -------------------- fused RMSNorm + RoPE on fused QKV buffer --------------------
__global__ __launch_bounds__(128) void norm_rope_kernel(float* __restrict__ QKV,
                                                        const float* __restrict__ qw,
                                                        const float* __restrict__ kw) {
    const int row = blockIdx.x;
    const int h   = blockIdx.y;
    const int d   = threadIdx.x;

    float* ptr;
    const float* w;
    if (h < NH) { ptr = QKV + (size_t)row * QKVN + h * HD;               w = qw; }
    else        { ptr = QKV + (size_t)row * QKVN + KOFF + (h - NH) * HD; w = kw; }

    float v = ptr[d];
    float ss = v * v;
#pragma unroll
    for (int o = 16; o > 0; o >>= 1) ss += __shfl_xor_sync(0xffffffffu, ss, o);

    __shared__ float wsum[4];
    if ((d & 31) == 0) wsum[d >> 5] = ss;
    __syncthreads();
    float tot = wsum[0] + wsum[1] + wsum[2] + wsum[3];
    float rn  = rsqrtf(tot * (1.0f / 128.0f) + 1e-6f);
    float vn  = v * rn * w[d];

    __shared__ float sv[128];
    sv[d] = vn;
    __syncthreads();

    const int s = row & (SS - 1);
    const int i = d & 63;
    float c  = g_cos[s * 64 + i];
    float sn = g_sin[s * 64 + i];
    float t1 = sv[i];
    float t2 = sv[i + 64];
    float out = (d < 64) ? (t1 * c - t2 * sn) : (t1 * sn + t2 * c);
    ptr[d] = to_tf32(out);
}

// ==================== tensor-core flash attention (tf32, unchanged core) ============
#define QSTR 132
#define KSTR 132
#define VSTR 136
#define FL_SMEM ((128*QSTR + 2*64*KSTR + 2*64*VSTR) * 4)   // 204800 B

__global__ __launch_bounds__(256, 1) void flash_mma(const float* __restrict__ QKV,
                                                    __half* __restrict__ O) {
    extern __shared__ float sm[];
    float* Qs = sm;
    float* Ks = Qs + 128 * QSTR;
    float* Vs = Ks + 2 * 64 * KSTR;

    const int qi   = (int)gridDim.x - 1 - (int)blockIdx.x;
    const int h    = blockIdx.y;
    const int b    = blockIdx.z;
    const int kvh  = h >> 2;
    const int tid  = threadIdx.x;
    const int lane = tid & 31;
    const int w    = tid >> 5;
    const int g    = lane >> 2;
    const int tg   = lane & 3;
    const int qs   = qi * 128;
    const int ntiles = 2 * qi + 2;
    const float scl = 0.08838834764831845f * 1.4426950408889634f;

    const float* Qg = QKV + (size_t)(b * SS + qs) * QKVN + h * HD;
    const float* Kg = QKV + (size_t)(b * SS) * QKVN + KOFF + kvh * HD;
    const float* Vg = QKV + (size_t)(b * SS) * QKVN + VOFF + kvh * HD;

    for (int i = tid; i < 128 * 32; i += 256) {
        int r = i >> 5, c4 = i & 31;
        *(float4*)(Qs + r * QSTR + c4 * 4) =
            *(const float4*)(Qg + (size_t)r * QKVN + c4 * 4);
    }

    for (int i = tid; i < 64 * 32; i += 256) {
        int r = i >> 5, c4 = i & 31;
        const float* kg = Kg + (size_t)r * QKVN + c4 * 4;
        const float* vg = Vg + (size_t)r * QKVN + c4 * 4;
        unsigned ka = (unsigned)__cvta_generic_to_shared(Ks + r * KSTR + c4 * 4);
        unsigned va = (unsigned)__cvta_generic_to_shared(Vs + r * VSTR + c4 * 4);
        CP_ASYNC16(ka, kg);
        CP_ASYNC16(va, vg);
    }
    CP_COMMIT();

    float m0 = -1e30f, m1 = -1e30f, l0 = 0.f, l1 = 0.f;
    float acc[16][4];
#pragma unroll
    for (int nt = 0; nt < 16; ++nt)
#pragma unroll
        for (int c = 0; c < 4; ++c) acc[nt][c] = 0.f;

    const int rowg0 = qs + w * 16 + g;
    const int rowg1 = rowg0 + 8;
    const int srcA  = (g << 2) | (tg >> 1);
    const int srcB  = srcA + 2;
    const bool odd  = (tg & 1);

    for (int kt = 0; kt < ntiles; ++kt) {
        __syncthreads();
        if (kt + 1 < ntiles) {
            int bf = (kt + 1) & 1;
            int ks0 = (kt + 1) * 64;
            float* Kw = Ks + bf * 64 * KSTR;
            float* Vw = Vs + bf * 64 * VSTR;
            for (int i = tid; i < 64 * 32; i += 256) {
                int r = i >> 5, c4 = i & 31;
                const float* kg = Kg + (size_t)(ks0 + r) * QKVN + c4 * 4;
                const float* vg = Vg + (size_t)(ks0 + r) * QKVN + c4 * 4;
                unsigned ka = (unsigned)__cvta_generic_to_shared(Kw + r * KSTR + c4 * 4);
                unsigned va = (unsigned)__cvta_generic_to_shared(Vw + r * VSTR + c4 * 4);
                CP_ASYNC16(ka, kg);
                CP_ASYNC16(va, vg);
            }
            CP_COMMIT();
            CP_WAIT1();
        } else {
            CP_WAIT0();
        }
        __syncthreads();

        const float* Kb = Ks + (kt & 1) * 64 * KSTR;
        const float* Vb = Vs + (kt & 1) * 64 * VSTR;

        float sacc[8][4];
#pragma unroll
        for (int nt = 0; nt < 8; ++nt)
#pragma unroll
            for (int c = 0; c < 4; ++c) sacc[nt][c] = 0.f;

#pragma unroll
        for (int ka = 0; ka < 16; ++ka) {
            const int k0 = ka * 8;
            const float* qp = Qs + (size_t)(w * 16 + g) * QSTR + k0 + tg;
            uint32_t a0 = __float_as_uint(qp[0]);
            uint32_t a1 = __float_as_uint(qp[8 * QSTR]);
            uint32_t a2 = __float_as_uint(qp[4]);
            uint32_t a3 = __float_as_uint(qp[8 * QSTR + 4]);
#pragma unroll
            for (int nt = 0; nt < 8; ++nt) {
                const float* kp = Kb + (size_t)(nt * 8 + g) * KSTR + k0 + tg;
                uint32_t b0 = __float_as_uint(kp[0]);
                uint32_t b1 = __float_as_uint(kp[4]);
                mma_tf32(sacc[nt][0], sacc[nt][1], sacc[nt][2], sacc[nt][3],
                         a0, a1, a2, a3, b0, b1);
            }
        }

        const bool need_mask = (kt >= 2 * qi);
        float mx0 = -1e30f, mx1 = -1e30f;
#pragma unroll
        for (int nt = 0; nt < 8; ++nt) {
            int c0 = kt * 64 + nt * 8 + 2 * tg;
            int c1 = c0 + 1;
            float v0 = sacc[nt][0] * scl, v1 = sacc[nt][1] * scl;
            float v2 = sacc[nt][2] * scl, v3 = sacc[nt][3] * scl;
            if (need_mask) {
                if (c0 > rowg0) v0 = -1e30f;
                if (c1 > rowg0) v1 = -1e30f;
                if (c0 > rowg1) v2 = -1e30f;
                if (c1 > rowg1) v3 = -1e30f;
            }
            sacc[nt][0] = v0; sacc[nt][1] = v1; sacc[nt][2] = v2; sacc[nt][3] = v3;
            mx0 = fmaxf(mx0, fmaxf(v0, v1));
            mx1 = fmaxf(mx1, fmaxf(v2, v3));
        }
        mx0 = fmaxf(mx0, __shfl_xor_sync(0xffffffffu, mx0, 1));
        mx0 = fmaxf(mx0, __shfl_xor_sync(0xffffffffu, mx0, 2));
        mx1 = fmaxf(mx1, __shfl_xor_sync(0xffffffffu, mx1, 1));
        mx1 = fmaxf(mx1, __shfl_xor_sync(0xffffffffu, mx1, 2));

        float mn0 = fmaxf(m0, mx0), mn1 = fmaxf(m1, mx1);
        float al0 = exp2f(m0 - mn0), al1 = exp2f(m1 - mn1);
        m0 = mn0; m1 = mn1;

        float ps0 = 0.f, ps1 = 0.f;
#pragma unroll
        for (int nt = 0; nt < 8; ++nt) {
            float p0 = exp2f(sacc[nt][0] - mn0);
            float p1 = exp2f(sacc[nt][1] - mn0);
            float p2 = exp2f(sacc[nt][2] - mn1);
            float p3 = exp2f(sacc[nt][3] - mn1);
            ps0 += p0 + p1; ps1 += p2 + p3;
            sacc[nt][0] = to_tf32(p0); sacc[nt][1] = to_tf32(p1);
            sacc[nt][2] = to_tf32(p2); sacc[nt][3] = to_tf32(p3);
        }
        ps0 += __shfl_xor_sync(0xffffffffu, ps0, 1);
        ps0 += __shfl_xor_sync(0xffffffffu, ps0, 2);
        ps1 += __shfl_xor_sync(0xffffffffu, ps1, 1);
        ps1 += __shfl_xor_sync(0xffffffffu, ps1, 2);
        l0 = l0 * al0 + ps0;
        l1 = l1 * al1 + ps1;

#pragma unroll
        for (int nt = 0; nt < 16; ++nt) {
            acc[nt][0] *= al0; acc[nt][1] *= al0;
            acc[nt][2] *= al1; acc[nt][3] *= al1;
        }

#pragma unroll
        for (int ka = 0; ka < 8; ++ka) {
            float e0 = __shfl_sync(0xffffffffu, sacc[ka][0], srcA);
            float e1 = __shfl_sync(0xffffffffu, sacc[ka][1], srcA);
            float e2 = __shfl_sync(0xffffffffu, sacc[ka][2], srcA);
            float e3 = __shfl_sync(0xffffffffu, sacc[ka][3], srcA);
            float f0 = __shfl_sync(0xffffffffu, sacc[ka][0], srcB);
            float f1 = __shfl_sync(0xffffffffu, sacc[ka][1], srcB);
            float f2 = __shfl_sync(0xffffffffu, sacc[ka][2], srcB);
            float f3 = __shfl_sync(0xffffffffu, sacc[ka][3], srcB);
            uint32_t pa0 = __float_as_uint(odd ? e1 : e0);
            uint32_t pa1 = __float_as_uint(odd ? e3 : e2);
            uint32_t pa2 = __float_as_uint(odd ? f1 : f0);
            uint32_t pa3 = __float_as_uint(odd ? f3 : f2);
            const int k0 = ka * 8;
#pragma unroll
            for (int nt = 0; nt < 16; ++nt) {
                const float* vp = Vb + (size_t)(k0 + tg) * VSTR + nt * 8 + g;
                uint32_t b0 = __float_as_uint(vp[0]);
                uint32_t b1 = __float_as_uint(vp[4 * VSTR]);
                mma_tf32(acc[nt][0], acc[nt][1], acc[nt][2], acc[nt][3],
                         pa0, pa1, pa2, pa3, b0, b1);
            }
        }
    }

    // epilogue: normalize + write ctx as fp16 (A operand of the wo GEMM)
    float inv0 = 1.0f / l0, inv1 = 1.0f / l1;
    __half* Og = O + (size_t)(b * SS + qs + w * 16) * (NH * HD) + h * HD;
#pragma unroll
    for (int nt = 0; nt < 16; ++nt) {
        int col = nt * 8 + 2 * tg;
        __half2 h0 = __floats2half2_rn(acc[nt][0] * inv0, acc[nt][1] * inv0);
        __half2 h1 = __floats2half2_rn(acc[nt][2] * inv1, acc[nt][3] * inv1);
        *(uint32_t*)(Og + (size_t)g * (NH * HD) + col)       = *(uint32_t*)&h0;
        *(uint32_t*)(Og + (size_t)(g + 8) * (NH * HD) + col) = *(uint32_t*)&h1;
    }
}

// -------------------- launch --------------------
extern "C" void kernel_launch(void* const* d_in, const int* in_sizes, int n_in,
                              void* d_out, int out_size) {
    const float* x  = (const float*)d_in[0];
    const float* wq = (const float*)d_in[1];
    const float* wk = (const float*)d_in[2];
    const float* wv = (const float*)d_in[3];
    const float* wo = (const float*)d_in[4];
    const float* qw = (const float*)d_in[5];
    const float* kw = (const float*)d_in[6];
    float* out = (float*)d_out;

    float *qkv; __half *ctx, *xh; uint32_t *wp;
    cudaGetSymbolAddress((void**)&qkv, g_qkv);
    cudaGetSymbolAddress((void**)&ctx, g_ctx);
    cudaGetSymbolAddress((void**)&xh,  g_xh);
    cudaGetSymbolAddress((void**)&wp,  g_wp);

    cudaFuncSetAttribute(gemm_f16,  cudaFuncAttributeMaxDynamicSharedMemorySize, GEMM_SMEM);
    cudaFuncSetAttribute(flash_mma, cudaFuncAttributeMaxDynamicSharedMemorySize, FL_SMEM);

    // fp16 activations + rope tables
    pack_x<<<(MROWS * HH / 4) / 256, 256>>>(x, xh);
    rope_table_kernel<<<64, 1024>>>();

    // fused QKV packed-weight concat: wp[K/2=2048][6144] = [wq | wk | wv]
    pack_weight<<<((HH/2) * (4096/4)) / 256, 256>>>(wq, wp, 4096/4, 4096, QKVN, 0);
    pack_weight<<<((HH/2) * (1024/4)) / 256, 256>>>(wk, wp, 1024/4, 1024, QKVN, KOFF);
    pack_weight<<<((HH/2) * (1024/4)) / 256, 256>>>(wv, wp, 1024/4, 1024, QKVN, VOFF);

    // fused QKV projection (fp16 mma); tf32-round V columns (>= VOFF) in epilogue
    gemm_f16<<<dim3(QKVN / 128, 16), 256, GEMM_SMEM>>>(xh, wp, qkv, MROWS, QKVN, HH, VOFF);

    // RMSNorm + RoPE (tf32 out) on Q and K inside the fused buffer
    norm_rope_kernel<<<dim3(MROWS, NH + NKV), 128>>>(qkv, qw, kw);

    // causal GQA attention (tf32 tensor cores); writes ctx as fp16
    flash_mma<<<dim3(SS / 128, NH, BB), 256, FL_SMEM>>>(qkv, ctx);

    // output projection (fp16 mma)
    pack_weight<<<((4096/2) * (4096/4)) / 256, 256>>>(wo, wp, 4096/4, 4096, 4096, 0);
    gemm_f16<<<dim3(32, 16), 256, GEMM_SMEM>>>(ctx, wp, out, MROWS, 4096, 4096, 1 << 30);
}

// round 14
// speedup vs baseline: 2.7619x; 1.0882x over previous
#include <cuda_runtime.h>
#include <cuda_fp16.h>
#include <math.h>
#include <stdint.h>

// Problem constants
#define BB   2
#define SS   1024
#define HH   4096
#define NH   32
#define NKV  8
#define HD   128
#define MROWS (BB*SS)             // 2048
#define QKVN (NH*HD + 2*NKV*HD)   // 6144 fused QKV width
#define KOFF (NH*HD)              // 4096
#define VOFF (NH*HD + NKV*HD)     // 5120

// -------------------- scratch (device globals; no allocation) --------------------
__device__ float    g_qkv[MROWS * QKVN];        // fused Q|K|V fp32 (GEMM out)
__device__ __half   g_qh [MROWS * NH * HD];     // Q fp16 rows (post norm+rope)
__device__ uint32_t g_kh [BB*NKV * SS * (HD/2)];   // K packed {d,d+1}: [bh][key][dp]
__device__ uint32_t g_vh [BB*NKV * (SS/2) * HD];   // V packed {k,k+1}: [bh][kp][d]
__device__ __half   g_ctx[MROWS * NH * HD];     // ctx fp16 (feeds wo GEMM)
__device__ __half   g_xh [MROWS * HH];          // fp16 x
__device__ uint32_t g_wp [(HH/2) * QKVN];       // packed {k,k+1} half2 weights (reused)
__device__ float    g_cos[SS * (HD/2)];
__device__ float    g_sin[SS * (HD/2)];

// fp16 tensor-core mma: D(16x8,f32) += A(16x16,f16) * B(16x8,f16)
__device__ __forceinline__ void mma_f16(float& d0, float& d1, float& d2, float& d3,
                                        uint32_t a0, uint32_t a1, uint32_t a2, uint32_t a3,
                                        uint32_t b0, uint32_t b1) {
    asm volatile("mma.sync.aligned.m16n8k16.row.col.f32.f16.f16.f32 "
                 "{%0,%1,%2,%3},{%4,%5,%6,%7},{%8,%9},{%0,%1,%2,%3};"
                 : "+f"(d0), "+f"(d1), "+f"(d2), "+f"(d3)
                 : "r"(a0), "r"(a1), "r"(a2), "r"(a3), "r"(b0), "r"(b1));
}

__device__ __forceinline__ uint32_t packh2(float lo, float hi) {
    __half2 h = __floats2half2_rn(lo, hi);
    return *(uint32_t*)&h;
}

#define CP_ASYNC16(saddr, gptr) \
    asm volatile("cp.async.cg.shared.global [%0], [%1], 16;" :: "r"(saddr), "l"(gptr))
#define CP_COMMIT() asm volatile("cp.async.commit_group;")
#define CP_WAIT1()  asm volatile("cp.async.wait_group 1;")
#define CP_WAIT0()  asm volatile("cp.async.wait_group 0;")

// ==================== FP16 tensor-core GEMM (cp.async 3-stage, 2 CTA/SM) ============
#define ASTW 20
#define BSTW 136
#define STGW (128*ASTW + 16*BSTW)          // 4736 u32 = 18944 B
#define GEMM_SMEM (3 * STGW * 4)           // 56832 B

__device__ __forceinline__ void stage_tile(int tid, uint32_t* smbase,
                                           const __half* __restrict__ Ag,
                                           const uint32_t* __restrict__ Bg,
                                           int N, int K, int t) {
    uint32_t* As = smbase + (t % 3) * STGW;
    uint32_t* Bs = As + 128 * ASTW;
#pragma unroll
    for (int i = 0; i < 2; ++i) {
        int e = tid + i * 256;
        int r = e >> 2, c = e & 3;
        unsigned d = (unsigned)__cvta_generic_to_shared(As + r * ASTW + c * 4);
        CP_ASYNC16(d, Ag + (size_t)r * K + t * 32 + c * 8);
    }
#pragma unroll
    for (int i = 0; i < 2; ++i) {
        int e = tid + i * 256;
        int r = e >> 5, c = e & 31;
        unsigned d = (unsigned)__cvta_generic_to_shared(Bs + r * BSTW + c * 4);
        CP_ASYNC16(d, Bg + (size_t)(t * 16 + r) * N + c * 4);
    }
    CP_COMMIT();
}

__global__ __launch_bounds__(256, 2) void gemm_f16(const __half* __restrict__ A,
                                                   const uint32_t* __restrict__ Bp,
                                                   float* __restrict__ C,
                                                   int M, int N, int K) {
    extern __shared__ uint32_t smw[];

    const int tid  = threadIdx.x;
    const int lane = tid & 31;
    const int w    = tid >> 5;
    const int g    = lane >> 2;
    const int tg   = lane & 3;
    const int wm   = (w & 1) * 64;
    const int wn   = (w >> 1) * 32;
    const int bm   = blockIdx.y * 128;
    const int bn   = blockIdx.x * 128;

    const __half*   Ag = A  + (size_t)bm * K;
    const uint32_t* Bg = Bp + bn;
    const int T = K >> 5;

    stage_tile(tid, smw, Ag, Bg, N, K, 0);
    stage_tile(tid, smw, Ag, Bg, N, K, 1);

    float acc[4][4][4];
#pragma unroll
    for (int mi = 0; mi < 4; ++mi)
#pragma unroll
        for (int ni = 0; ni < 4; ++ni)
#pragma unroll
            for (int c = 0; c < 4; ++c) acc[mi][ni][c] = 0.f;

    for (int t = 0; t < T; ++t) {
        if (t < T - 1) CP_WAIT1();
        else           CP_WAIT0();
        __syncthreads();
        if (t + 2 < T) stage_tile(tid, smw, Ag, Bg, N, K, t + 2);

        const uint32_t* Ab = smw + (t % 3) * STGW;
        const uint32_t* Bb = Ab + 128 * ASTW;

#pragma unroll
        for (int ks = 0; ks < 2; ++ks) {
            const int k0w = ks * 8;
            uint32_t af[4][4], bf[4][2];
#pragma unroll
            for (int mi = 0; mi < 4; ++mi) {
                const uint32_t* p = Ab + (size_t)(wm + mi * 16 + g) * ASTW + k0w + tg;
                af[mi][0] = p[0];
                af[mi][1] = p[8 * ASTW];
                af[mi][2] = p[4];
                af[mi][3] = p[8 * ASTW + 4];
            }
#pragma unroll
            for (int ni = 0; ni < 4; ++ni) {
                const uint32_t* p = Bb + (size_t)(k0w + tg) * BSTW + wn + ni * 8 + g;
                bf[ni][0] = p[0];
                bf[ni][1] = p[4 * BSTW];
            }
#pragma unroll
            for (int mi = 0; mi < 4; ++mi)
#pragma unroll
                for (int ni = 0; ni < 4; ++ni)
                    mma_f16(acc[mi][ni][0], acc[mi][ni][1], acc[mi][ni][2], acc[mi][ni][3],
                            af[mi][0], af[mi][1], af[mi][2], af[mi][3],
                            bf[ni][0], bf[ni][1]);
        }
    }

#pragma unroll
    for (int mi = 0; mi < 4; ++mi) {
        int r0 = bm + wm + mi * 16 + g;
#pragma unroll
        for (int ni = 0; ni < 4; ++ni) {
            int c0 = bn + wn + ni * 8 + 2 * tg;
            float2 v0 = {acc[mi][ni][0], acc[mi][ni][1]};
            float2 v1 = {acc[mi][ni][2], acc[mi][ni][3]};
            *(float2*)(C + (size_t)r0 * N + c0)       = v0;
            *(float2*)(C + (size_t)(r0 + 8) * N + c0) = v1;
        }
    }
}

// -------------------- x -> fp16 copy --------------------
__global__ void pack_x(const float* __restrict__ in, __half* __restrict__ outp) {
    int i = blockIdx.x * 256 + threadIdx.x;
    float4 v = ((const float4*)in)[i];
    uint2 u = {packh2(v.x, v.y), packh2(v.z, v.w)};
    ((uint2*)outp)[i] = u;
}

// -------------------- weight -> packed {k,k+1} half2 words --------------------
__global__ void pack_weight(const float* __restrict__ in, uint32_t* __restrict__ outp,
                            int Nw4, int Nw, int Nout, int off) {
    int i = blockIdx.x * 256 + threadIdx.x;
    int kp = i / Nw4, c = i - kp * Nw4;
    float4 r0 = *(const float4*)(in + (size_t)(2 * kp)     * Nw + c * 4);
    float4 r1 = *(const float4*)(in + (size_t)(2 * kp + 1) * Nw + c * 4);
    uint4 u = {packh2(r0.x, r1.x), packh2(r0.y, r1.y),
               packh2(r0.z, r1.z), packh2(r0.w, r1.w)};
    *(uint4*)(outp + (size_t)kp * Nout + off + c * 4) = u;
}

// -------------------- V -> packed {key,key+1} half2 words --------------------
// g_vh[(b*NKV+kvh)*(SS/2) + kp][d] = {V[2kp][d], V[2kp+1][d]}
__global__ void v_pack(const float* __restrict__ QKV, uint32_t* __restrict__ outp) {
    int i = blockIdx.x * 256 + threadIdx.x;     // word index
    int d   = i & (HD - 1);
    int kp  = (i >> 7) & (SS/2 - 1);
    int bh  = i >> 16;                          // 0..15
    int b   = bh >> 3, kvh = bh & 7;
    size_t base = (size_t)(b * SS + 2 * kp) * QKVN + VOFF + kvh * HD + d;
    float v0 = QKV[base];
    float v1 = QKV[base + QKVN];
    outp[i] = packh2(v0, v1);
}

// -------------------- RoPE cos/sin table --------------------
__global__ __launch_bounds__(1024) void rope_table_kernel() {
    __shared__ double sinv[64];
    const int tid = threadIdx.x;
    if (tid < 64) sinv[tid] = exp(-(double)tid / 64.0 * log(10000.0));
    __syncthreads();
    const int f = tid & 63;
    const int s = blockIdx.x * 16 + (tid >> 6);
    double a = (double)s * sinv[f];
    double q = rint(a * 0.15915494309189535);
    float r = (float)(a - q * 6.283185307179586);
    float sc, cc;
    __sincosf(r, &sc, &cc);
    g_cos[s * 64 + f] = cc;
    g_sin[s * 64 + f] = sc;
}

// -------------------- fused RMSNorm + RoPE -> fp16 outputs --------------------
// Q heads -> g_qh half rows; K heads -> g_kh packed {d,d+1} words [key][dp]
__global__ __launch_bounds__(128) void norm_rope_kernel(const float* __restrict__ QKV,
                                                        __half* __restrict__ Qh,
                                                        uint32_t* __restrict__ Kp,
                                                        const float* __restrict__ qw,
                                                        const float* __restrict__ kw) {
    const int row = blockIdx.x;       // 0..2047
    const int h   = blockIdx.y;       // 0..39
    const int d   = threadIdx.x;

    const float* ptr;
    const float* w;
    if (h < NH) { ptr = QKV + (size_t)row * QKVN + h * HD;               w = qw; }
    else        { ptr = QKV + (size_t)row * QKVN + KOFF + (h - NH) * HD; w = kw; }

    float v = ptr[d];
    float ss = v * v;
#pragma unroll
    for (int o = 16; o > 0; o >>= 1) ss += __shfl_xor_sync(0xffffffffu, ss, o);

    __shared__ float wsum[4];
    if ((d & 31) == 0) wsum[d >> 5] = ss;
    __syncthreads();
    float tot = wsum[0] + wsum[1] + wsum[2] + wsum[3];
    float rn  = rsqrtf(tot * (1.0f / 128.0f) + 1e-6f);
    float vn  = v * rn * w[d];

    __shared__ float sv[128];
    sv[d] = vn;
    __syncthreads();

    const int s = row & (SS - 1);
    const int i = d & 63;
    float c  = g_cos[s * 64 + i];
    float sn = g_sin[s * 64 + i];
    float t1 = sv[i];
    float t2 = sv[i + 64];
    float out = (d < 64) ? (t1 * c - t2 * sn) : (t1 * sn + t2 * c);

    if (h < NH) {
        Qh[(size_t)row * (NH * HD) + h * HD + d] = __float2half(out);
    } else {
        __shared__ float so[128];
        so[d] = out;
        __syncthreads();
        if (d < 64) {
            int b = row >> 10;
            uint32_t word = packh2(so[2 * d], so[2 * d + 1]);
            Kp[((size_t)(b * NKV + (h - NH)) * SS + s) * (HD/2) + d] = word;
        }
    }
}

// ==================== fp16 tensor-core flash attention ====================
// BM=128, BN=64, 8 warps. Q fp16 resident; K/V packed fp16 double-buffered via
// cp.async. QK^T and PV on mma.m16n8k16; softmax fp32 log2 domain.
// Qs/Ks: u32 stride 68 (banks g*4+tg distinct); Vs: stride 136 (tg*8+g distinct).
#define QW 68
#define KW 68
#define VW 136
#define FL_SMEM ((128*QW + 2*64*KW + 2*32*VW) * 4)   // 104448 B

__global__ __launch_bounds__(256, 2) void flash_h(const __half* __restrict__ Qh,
                                                  const uint32_t* __restrict__ Kp,
                                                  const uint32_t* __restrict__ Vp,
                                                  __half* __restrict__ O) {
    extern __shared__ uint32_t smu[];
    uint32_t* Qs = smu;                    // [128][QW]
    uint32_t* Ks = Qs + 128 * QW;          // [2][64][KW]   (key-major, dp words)
    uint32_t* Vs = Ks + 2 * 64 * KW;       // [2][32][VW]   (kp-major, d words)

    const int qi   = (int)gridDim.x - 1 - (int)blockIdx.x;
    const int h    = blockIdx.y;
    const int b    = blockIdx.z;
    const int kvh  = h >> 2;
    const int tid  = threadIdx.x;
    const int lane = tid & 31;
    const int w    = tid >> 5;
    const int g    = lane >> 2;
    const int tg   = lane & 3;
    const int qs   = qi * 128;
    const int ntiles = 2 * qi + 2;
    const float scl = 0.08838834764831845f * 1.4426950408889634f;

    const __half*   Qg = Qh + (size_t)(b * SS + qs) * (NH * HD) + h * HD;
    const uint32_t* Kg = Kp + (size_t)(b * NKV + kvh) * SS * (HD/2);
    const uint32_t* Vg = Vp + (size_t)(b * NKV + kvh) * (SS/2) * HD;

    // Q tile: 128 rows x 16 chunks of 16B
#pragma unroll
    for (int it = 0; it < 8; ++it) {
        int e = tid + it * 256;
        int r = e >> 4, c = e & 15;
        unsigned d = (unsigned)__cvta_generic_to_shared(Qs + r * QW + c * 4);
        CP_ASYNC16(d, Qg + (size_t)r * (NH * HD) + c * 8);
    }
    // K/V tile 0
#pragma unroll
    for (int it = 0; it < 4; ++it) {
        int e = tid + it * 256;
        int r = e >> 4, c = e & 15;
        unsigned d = (unsigned)__cvta_generic_to_shared(Ks + r * KW + c * 4);
        CP_ASYNC16(d, Kg + (size_t)r * (HD/2) + c * 4);
    }
#pragma unroll
    for (int it = 0; it < 4; ++it) {
        int e = tid + it * 256;
        int r = e >> 5, c = e & 31;
        unsigned d = (unsigned)__cvta_generic_to_shared(Vs + r * VW + c * 4);
        CP_ASYNC16(d, Vg + (size_t)r * HD + c * 4);
    }
    CP_COMMIT();

    float m0 = -1e30f, m1 = -1e30f, l0 = 0.f, l1 = 0.f;
    float acc[16][4];
#pragma unroll
    for (int nt = 0; nt < 16; ++nt)
#pragma unroll
        for (int c = 0; c < 4; ++c) acc[nt][c] = 0.f;

    const int rowg0 = qs + w * 16 + g;
    const int rowg1 = rowg0 + 8;

    for (int kt = 0; kt < ntiles; ++kt) {
        __syncthreads();
        if (kt + 1 < ntiles) {
            int bf = (kt + 1) & 1;
            uint32_t* Kw2 = Ks + bf * 64 * KW;
            uint32_t* Vw2 = Vs + bf * 32 * VW;
            const uint32_t* kg = Kg + (size_t)(kt + 1) * 64 * (HD/2);
            const uint32_t* vg = Vg + (size_t)(kt + 1) * 32 * HD;
#pragma unroll
            for (int it = 0; it < 4; ++it) {
                int e = tid + it * 256;
                int r = e >> 4, c = e & 15;
                unsigned d = (unsigned)__cvta_generic_to_shared(Kw2 + r * KW + c * 4);
                CP_ASYNC16(d, kg + (size_t)r * (HD/2) + c * 4);
            }
#pragma unroll
            for (int it = 0; it < 4; ++it) {
                int e = tid + it * 256;
                int r = e >> 5, c = e & 31;
                unsigned d = (unsigned)__cvta_generic_to_shared(Vw2 + r * VW + c * 4);
                CP_ASYNC16(d, vg + (size_t)r * HD + c * 4);
            }
            CP_COMMIT();
            CP_WAIT1();
        } else {
            CP_WAIT0();
        }
        __syncthreads();

        const uint32_t* Kb = Ks + (kt & 1) * 64 * KW;
        const uint32_t* Vb = Vs + (kt & 1) * 32 * VW;

        // ---- S = Q @ K^T : 8 k16 steps over HD=128
        float sacc[8][4];
#pragma unroll
        for (int nt = 0; nt < 8; ++nt)
#pragma unroll
            for (int c = 0; c < 4; ++c) sacc[nt][c] = 0.f;

#pragma unroll
        for (int ks = 0; ks < 8; ++ks) {
            const uint32_t* qp = Qs + (size_t)(w * 16 + g) * QW + ks * 8 + tg;
            uint32_t a0 = qp[0];
            uint32_t a1 = qp[8 * QW];
            uint32_t a2 = qp[4];
            uint32_t a3 = qp[8 * QW + 4];
#pragma unroll
            for (int nt = 0; nt < 8; ++nt) {
                const uint32_t* kp = Kb + (size_t)(nt * 8 + g) * KW + ks * 8 + tg;
                mma_f16(sacc[nt][0], sacc[nt][1], sacc[nt][2], sacc[nt][3],
                        a0, a1, a2, a3, kp[0], kp[4]);
            }
        }

        // ---- online softmax (log2 domain)
        const bool need_mask = (kt >= 2 * qi);
        float mx0 = -1e30f, mx1 = -1e30f;
#pragma unroll
        for (int nt = 0; nt < 8; ++nt) {
            int c0 = kt * 64 + nt * 8 + 2 * tg;
            int c1 = c0 + 1;
            float v0 = sacc[nt][0] * scl, v1 = sacc[nt][1] * scl;
            float v2 = sacc[nt][2] * scl, v3 = sacc[nt][3] * scl;
            if (need_mask) {
                if (c0 > rowg0) v0 = -1e30f;
                if (c1 > rowg0) v1 = -1e30f;
                if (c0 > rowg1) v2 = -1e30f;
                if (c1 > rowg1) v3 = -1e30f;
            }
            sacc[nt][0] = v0; sacc[nt][1] = v1; sacc[nt][2] = v2; sacc[nt][3] = v3;
            mx0 = fmaxf(mx0, fmaxf(v0, v1));
            mx1 = fmaxf(mx1, fmaxf(v2, v3));
        }
        mx0 = fmaxf(mx0, __shfl_xor_sync(0xffffffffu, mx0, 1));
        mx0 = fmaxf(mx0, __shfl_xor_sync(0xffffffffu, mx0, 2));
        mx1 = fmaxf(mx1, __shfl_xor_sync(0xffffffffu, mx1, 1));
        mx1 = fmaxf(mx1, __shfl_xor_sync(0xffffffffu, mx1, 2));

        float mn0 = fmaxf(m0, mx0), mn1 = fmaxf(m1, mx1);
        float al0 = exp2f(m0 - mn0), al1 = exp2f(m1 - mn1);
        m0 = mn0; m1 = mn1;

        float ps0 = 0.f, ps1 = 0.f;
#pragma unroll
        for (int nt = 0; nt < 8; ++nt) {
            float p0 = exp2f(sacc[nt][0] - mn0);
            float p1 = exp2f(sacc[nt][1] - mn0);
            float p2 = exp2f(sacc[nt][2] - mn1);
            float p3 = exp2f(sacc[nt][3] - mn1);
            ps0 += p0 + p1; ps1 += p2 + p3;
            sacc[nt][0] = p0; sacc[nt][1] = p1;
            sacc[nt][2] = p2; sacc[nt][3] = p3;
        }
        ps0 += __shfl_xor_sync(0xffffffffu, ps0, 1);
        ps0 += __shfl_xor_sync(0xffffffffu, ps0, 2);
        ps1 += __shfl_xor_sync(0xffffffffu, ps1, 1);
        ps1 += __shfl_xor_sync(0xffffffffu, ps1, 2);
        l0 = l0 * al0 + ps0;
        l1 = l1 * al1 + ps1;

#pragma unroll
        for (int nt = 0; nt < 16; ++nt) {
            acc[nt][0] *= al0; acc[nt][1] *= al0;
            acc[nt][2] *= al1; acc[nt][3] *= al1;
        }

        // ---- O += P @ V : 4 k16 steps over 64 keys; P C-frag -> A-frag by pack
#pragma unroll
        for (int ks = 0; ks < 4; ++ks) {
            uint32_t a0 = packh2(sacc[2*ks][0],   sacc[2*ks][1]);
            uint32_t a1 = packh2(sacc[2*ks][2],   sacc[2*ks][3]);
            uint32_t a2 = packh2(sacc[2*ks+1][0], sacc[2*ks+1][1]);
            uint32_t a3 = packh2(sacc[2*ks+1][2], sacc[2*ks+1][3]);
#pragma unroll
            for (int nt = 0; nt < 16; ++nt) {
                const uint32_t* vp = Vb + (size_t)(ks * 8 + tg) * VW + nt * 8 + g;
                mma_f16(acc[nt][0], acc[nt][1], acc[nt][2], acc[nt][3],
                        a0, a1, a2, a3, vp[0], vp[4 * VW]);
            }
        }
    }

    // epilogue: normalize + write ctx as fp16
    float inv0 = 1.0f / l0, inv1 = 1.0f / l1;
    __half* Og = O + (size_t)(b * SS + qs + w * 16) * (NH * HD) + h * HD;
#pragma unroll
    for (int nt = 0; nt < 16; ++nt) {
        int col = nt * 8 + 2 * tg;
        uint32_t h0 = packh2(acc[nt][0] * inv0, acc[nt][1] * inv0);
        uint32_t h1 = packh2(acc[nt][2] * inv1, acc[nt][3] * inv1);
        *(uint32_t*)(Og + (size_t)g * (NH * HD) + col)       = h0;
        *(uint32_t*)(Og + (size_t)(g + 8) * (NH * HD) + col) = h1;
    }
}

// -------------------- launch --------------------
extern "C" void kernel_launch(void* const* d_in, const int* in_sizes, int n_in,
                              void* d_out, int out_size) {
    const float* x  = (const float*)d_in[0];
    const float* wq = (const float*)d_in[1];
    const float* wk = (const float*)d_in[2];
    const float* wv = (const float*)d_in[3];
    const float* wo = (const float*)d_in[4];
    const float* qw = (const float*)d_in[5];
    const float* kw = (const float*)d_in[6];
    float* out = (float*)d_out;

    float *qkv; __half *qh, *ctx, *xh; uint32_t *kp, *vp, *wp;
    cudaGetSymbolAddress((void**)&qkv, g_qkv);
    cudaGetSymbolAddress((void**)&qh,  g_qh);
    cudaGetSymbolAddress((void**)&kp,  g_kh);
    cudaGetSymbolAddress((void**)&vp,  g_vh);
    cudaGetSymbolAddress((void**)&ctx, g_ctx);
    cudaGetSymbolAddress((void**)&xh,  g_xh);
    cudaGetSymbolAddress((void**)&wp,  g_wp);

    cudaFuncSetAttribute(gemm_f16, cudaFuncAttributeMaxDynamicSharedMemorySize, GEMM_SMEM);
    cudaFuncSetAttribute(flash_h,  cudaFuncAttributeMaxDynamicSharedMemorySize, FL_SMEM);

    // fp16 activations + rope tables
    pack_x<<<(MROWS * HH / 4) / 256, 256>>>(x, xh);
    rope_table_kernel<<<64, 1024>>>();

    // fused QKV packed-weight concat: wp[K/2=2048][6144] = [wq | wk | wv]
    pack_weight<<<((HH/2) * (4096/4)) / 256, 256>>>(wq, wp, 4096/4, 4096, QKVN, 0);
    pack_weight<<<((HH/2) * (1024/4)) / 256, 256>>>(wk, wp, 1024/4, 1024, QKVN, KOFF);
    pack_weight<<<((HH/2) * (1024/4)) / 256, 256>>>(wv, wp, 1024/4, 1024, QKVN, VOFF);

    // fused QKV projection (fp16 mma, fp32 out)
    gemm_f16<<<dim3(QKVN / 128, 16), 256, GEMM_SMEM>>>(xh, wp, qkv, MROWS, QKVN, HH);

    // RMSNorm + RoPE -> Q fp16 rows, K packed words; V -> packed words
    norm_rope_kernel<<<dim3(MROWS, NH + NKV), 128>>>(qkv, qh, kp, qw, kw);
    v_pack<<<(BB * NKV * (SS/2) * HD) / 256, 256>>>(qkv, vp);

    // causal GQA attention, all-fp16 tensor cores
    flash_h<<<dim3(SS / 128, NH, BB), 256, FL_SMEM>>>(qh, kp, vp, ctx);

    // output projection (fp16 mma)
    pack_weight<<<((4096/2) * (4096/4)) / 256, 256>>>(wo, wp, 4096/4, 4096, 4096, 0);
    gemm_f16<<<dim3(32, 16), 256, GEMM_SMEM>>>(ctx, wp, out, MROWS, 4096, 4096);
}

// round 16
// speedup vs baseline: 2.9042x; 1.0515x over previous
#include <cuda_runtime.h>
#include <cuda_fp16.h>
#include <math.h>
#include <stdint.h>

// Problem constants
#define BB   2
#define SS   1024
#define HH   4096
#define NH   32
#define NKV  8
#define HD   128
#define MROWS (BB*SS)             // 2048
#define QKVN (NH*HD + 2*NKV*HD)   // 6144 fused QKV width
#define KOFF (NH*HD)              // 4096
#define VOFF (NH*HD + NKV*HD)     // 5120

// -------------------- scratch (device globals; no allocation) --------------------
__device__ float    g_qkv[MROWS * QKVN];        // fused Q|K|V fp32 (GEMM out)
__device__ __half   g_qh [MROWS * NH * HD];     // Q fp16 rows (post norm+rope)
__device__ uint32_t g_kh [BB*NKV * SS * (HD/2)];   // K packed {d,d+1}: [bh][key][dp]
__device__ uint32_t g_vh [BB*NKV * (SS/2) * HD];   // V packed {k,k+1}: [bh][kp][d]
__device__ __half   g_ctx[MROWS * NH * HD];     // ctx fp16 (feeds wo GEMM)
__device__ __half   g_xh [MROWS * HH];          // fp16 x
__device__ uint32_t g_wp [QKVN * (HH/2)];       // packed TRANSPOSED weights [n][kp]
__device__ float    g_cos[SS * (HD/2)];
__device__ float    g_sin[SS * (HD/2)];

// fp16 tensor-core mma: D(16x8,f32) += A(16x16,f16) * B(16x8,f16)
__device__ __forceinline__ void mma_f16(float& d0, float& d1, float& d2, float& d3,
                                        uint32_t a0, uint32_t a1, uint32_t a2, uint32_t a3,
                                        uint32_t b0, uint32_t b1) {
    asm volatile("mma.sync.aligned.m16n8k16.row.col.f32.f16.f16.f32 "
                 "{%0,%1,%2,%3},{%4,%5,%6,%7},{%8,%9},{%0,%1,%2,%3};"
                 : "+f"(d0), "+f"(d1), "+f"(d2), "+f"(d3)
                 : "r"(a0), "r"(a1), "r"(a2), "r"(a3), "r"(b0), "r"(b1));
}

__device__ __forceinline__ void ldsm_x4(uint32_t& r0, uint32_t& r1,
                                        uint32_t& r2, uint32_t& r3, uint32_t addr) {
    asm volatile("ldmatrix.sync.aligned.m8n8.x4.shared.b16 {%0,%1,%2,%3}, [%4];"
                 : "=r"(r0), "=r"(r1), "=r"(r2), "=r"(r3) : "r"(addr));
}

__device__ __forceinline__ uint32_t packh2(float lo, float hi) {
    __half2 h = __floats2half2_rn(lo, hi);
    return *(uint32_t*)&h;
}

#define CP_ASYNC16(saddr, gptr) \
    asm volatile("cp.async.cg.shared.global [%0], [%1], 16;" :: "r"(saddr), "l"(gptr))
#define CP_COMMIT() asm volatile("cp.async.commit_group;")
#define CP_WAIT1()  asm volatile("cp.async.wait_group 1;")
#define CP_WAIT0()  asm volatile("cp.async.wait_group 0;")

// ==================== FP16 GEMM, ldmatrix fragments (3-stage, 2 CTA/SM) =============
// C[M,N](f32) = A[M,K](f16 rows) @ Bt (packed TRANSPOSED half2 words [N][K/2]).
// 128x128 block, BK=32, 256 threads, warp tile 64x32, mma.m16n8k16.
// A smem: 128 rows x 20 u32 (16 data + pad); B smem: 128 n-rows x 20 u32.
// ldmatrix row-start banks r*20%32 = {0,20,8,28,16,4,24,12}: conflict-free.
#define ASTW 20
#define BSTN 20
#define STGW (128*ASTW + 128*BSTN)         // 5120 u32 = 20480 B
#define GEMM_SMEM (3 * STGW * 4)           // 61440 B

__device__ __forceinline__ void stage_tile(int tid, uint32_t* smbase,
                                           const __half* __restrict__ Ag,
                                           const uint32_t* __restrict__ Bg,
                                           int Kp2, int K, int t) {
    uint32_t* As = smbase + (t % 3) * STGW;
    uint32_t* Bs = As + 128 * ASTW;
#pragma unroll
    for (int i = 0; i < 2; ++i) {
        int e = tid + i * 256;
        int r = e >> 2, c = e & 3;          // A: 128 rows x 4 chunks of 16B
        unsigned d = (unsigned)__cvta_generic_to_shared(As + r * ASTW + c * 4);
        CP_ASYNC16(d, Ag + (size_t)r * K + t * 32 + c * 8);
    }
#pragma unroll
    for (int i = 0; i < 2; ++i) {
        int e = tid + i * 256;
        int r = e >> 2, c = e & 3;          // B: 128 n-rows x 4 chunks of 16B
        unsigned d = (unsigned)__cvta_generic_to_shared(Bs + r * BSTN + c * 4);
        CP_ASYNC16(d, Bg + (size_t)r * Kp2 + t * 16 + c * 4);
    }
    CP_COMMIT();
}

__global__ __launch_bounds__(256, 2) void gemm_f16(const __half* __restrict__ A,
                                                   const uint32_t* __restrict__ Bt,
                                                   float* __restrict__ C,
                                                   int M, int N, int K) {
    extern __shared__ uint32_t smw[];

    const int tid  = threadIdx.x;
    const int lane = tid & 31;
    const int w    = tid >> 5;
    const int g    = lane >> 2;
    const int tg   = lane & 3;
    const int wm   = (w & 1) * 64;
    const int wn   = (w >> 1) * 32;
    const int bm   = blockIdx.y * 128;
    const int bn   = blockIdx.x * 128;

    // ldmatrix per-lane addressing
    const int aRow = lane & 15;                       // A: row within 16-row tile
    const int aOff = (lane >> 4) * 4;                 // A: word offset (k-half)
    const int bRow = (lane & 7) + ((lane >> 4) & 1) * 8;  // B: n-row within 16
    const int bOff = ((lane >> 3) & 1) * 4;           // B: word offset (k-half)

    const int Kp2 = K >> 1;
    const __half*   Ag = A  + (size_t)bm * K;
    const uint32_t* Bg = Bt + (size_t)bn * Kp2;
    const int T = K >> 5;
    const uint32_t sbase = (uint32_t)__cvta_generic_to_shared(smw);

    stage_tile(tid, smw, Ag, Bg, Kp2, K, 0);
    stage_tile(tid, smw, Ag, Bg, Kp2, K, 1);

    float acc[4][4][4];
#pragma unroll
    for (int mi = 0; mi < 4; ++mi)
#pragma unroll
        for (int ni = 0; ni < 4; ++ni)
#pragma unroll
            for (int c = 0; c < 4; ++c) acc[mi][ni][c] = 0.f;

    for (int t = 0; t < T; ++t) {
        if (t < T - 1) CP_WAIT1();
        else           CP_WAIT0();
        __syncthreads();
        if (t + 2 < T) stage_tile(tid, smw, Ag, Bg, Kp2, K, t + 2);

        const uint32_t Ab = sbase + ((t % 3) * STGW) * 4;
        const uint32_t Bb = Ab + 128 * ASTW * 4;
        const uint32_t aBase = Ab + ((wm + aRow) * ASTW + aOff) * 4;
        const uint32_t bBase = Bb + ((wn + bRow) * BSTN + bOff) * 4;

#pragma unroll
        for (int ks = 0; ks < 2; ++ks) {
            uint32_t af[4][4], bf[4][2];
#pragma unroll
            for (int mi = 0; mi < 4; ++mi)
                ldsm_x4(af[mi][0], af[mi][1], af[mi][2], af[mi][3],
                        aBase + (mi * 16 * ASTW + ks * 8) * 4);
#pragma unroll
            for (int np = 0; np < 2; ++np)
                ldsm_x4(bf[2*np][0], bf[2*np][1], bf[2*np+1][0], bf[2*np+1][1],
                        bBase + (np * 16 * BSTN + ks * 8) * 4);
#pragma unroll
            for (int mi = 0; mi < 4; ++mi)
#pragma unroll
                for (int ni = 0; ni < 4; ++ni)
                    mma_f16(acc[mi][ni][0], acc[mi][ni][1], acc[mi][ni][2], acc[mi][ni][3],
                            af[mi][0], af[mi][1], af[mi][2], af[mi][3],
                            bf[ni][0], bf[ni][1]);
        }
    }

#pragma unroll
    for (int mi = 0; mi < 4; ++mi) {
        int r0 = bm + wm + mi * 16 + g;
#pragma unroll
        for (int ni = 0; ni < 4; ++ni) {
            int c0 = bn + wn + ni * 8 + 2 * tg;
            float2 v0 = {acc[mi][ni][0], acc[mi][ni][1]};
            float2 v1 = {acc[mi][ni][2], acc[mi][ni][3]};
            *(float2*)(C + (size_t)r0 * N + c0)       = v0;
            *(float2*)(C + (size_t)(r0 + 8) * N + c0) = v1;
        }
    }
}

// -------------------- x -> fp16 copy --------------------
__global__ void pack_x(const float* __restrict__ in, __half* __restrict__ outp) {
    int i = blockIdx.x * 256 + threadIdx.x;
    float4 v = ((const float4*)in)[i];
    uint2 u = {packh2(v.x, v.y), packh2(v.z, v.w)};
    ((uint2*)outp)[i] = u;
}

// -------------------- weight -> packed TRANSPOSED half2 words --------------------
// in: [K][Nw] fp32 row-major. out[(off + n)*Kp2out + kp] = {in[2kp][n], in[2kp+1][n]}
__global__ __launch_bounds__(256) void pack_weight_t(const float* __restrict__ in,
                                                     uint32_t* __restrict__ outp,
                                                     int Nw, int Kp2out, int off) {
    __shared__ uint32_t ts[32][33];
    const int n0  = blockIdx.x * 32;
    const int kp0 = blockIdx.y * 32;
    const int tx = threadIdx.x & 31, ty = threadIdx.x >> 5;
#pragma unroll
    for (int i = 0; i < 4; ++i) {
        int kp = kp0 + ty + i * 8;
        float r0 = in[(size_t)(2 * kp)     * Nw + n0 + tx];
        float r1 = in[(size_t)(2 * kp + 1) * Nw + n0 + tx];
        ts[ty + i * 8][tx] = packh2(r0, r1);     // ts[kp_local][n_local]
    }
    __syncthreads();
#pragma unroll
    for (int i = 0; i < 4; ++i) {
        int nl = ty + i * 8;
        outp[(size_t)(off + n0 + nl) * Kp2out + kp0 + tx] = ts[tx][nl];
    }
}

// -------------------- V -> packed {key,key+1} half2 words --------------------
__global__ void v_pack(const float* __restrict__ QKV, uint32_t* __restrict__ outp) {
    int i = blockIdx.x * 256 + threadIdx.x;
    int d   = i & (HD - 1);
    int kp  = (i >> 7) & (SS/2 - 1);
    int bh  = i >> 16;
    int b   = bh >> 3, kvh = bh & 7;
    size_t base = (size_t)(b * SS + 2 * kp) * QKVN + VOFF + kvh * HD + d;
    float v0 = QKV[base];
    float v1 = QKV[base + QKVN];
    outp[i] = packh2(v0, v1);
}

// -------------------- RoPE cos/sin table --------------------
__global__ __launch_bounds__(1024) void rope_table_kernel() {
    __shared__ double sinv[64];
    const int tid = threadIdx.x;
    if (tid < 64) sinv[tid] = exp(-(double)tid / 64.0 * log(10000.0));
    __syncthreads();
    const int f = tid & 63;
    const int s = blockIdx.x * 16 + (tid >> 6);
    double a = (double)s * sinv[f];
    double q = rint(a * 0.15915494309189535);
    float r = (float)(a - q * 6.283185307179586);
    float sc, cc;
    __sincosf(r, &sc, &cc);
    g_cos[s * 64 + f] = cc;
    g_sin[s * 64 + f] = sc;
}

// -------------------- fused RMSNorm + RoPE -> fp16 outputs --------------------
__global__ __launch_bounds__(128) void norm_rope_kernel(const float* __restrict__ QKV,
                                                        __half* __restrict__ Qh,
                                                        uint32_t* __restrict__ Kp,
                                                        const float* __restrict__ qw,
                                                        const float* __restrict__ kw) {
    const int row = blockIdx.x;
    const int h   = blockIdx.y;
    const int d   = threadIdx.x;

    const float* ptr;
    const float* w;
    if (h < NH) { ptr = QKV + (size_t)row * QKVN + h * HD;               w = qw; }
    else        { ptr = QKV + (size_t)row * QKVN + KOFF + (h - NH) * HD; w = kw; }

    float v = ptr[d];
    float ss = v * v;
#pragma unroll
    for (int o = 16; o > 0; o >>= 1) ss += __shfl_xor_sync(0xffffffffu, ss, o);

    __shared__ float wsum[4];
    if ((d & 31) == 0) wsum[d >> 5] = ss;
    __syncthreads();
    float tot = wsum[0] + wsum[1] + wsum[2] + wsum[3];
    float rn  = rsqrtf(tot * (1.0f / 128.0f) + 1e-6f);
    float vn  = v * rn * w[d];

    __shared__ float sv[128];
    sv[d] = vn;
    __syncthreads();

    const int s = row & (SS - 1);
    const int i = d & 63;
    float c  = g_cos[s * 64 + i];
    float sn = g_sin[s * 64 + i];
    float t1 = sv[i];
    float t2 = sv[i + 64];
    float out = (d < 64) ? (t1 * c - t2 * sn) : (t1 * sn + t2 * c);

    if (h < NH) {
        Qh[(size_t)row * (NH * HD) + h * HD + d] = __float2half(out);
    } else {
        __shared__ float so[128];
        so[d] = out;
        __syncthreads();
        if (d < 64) {
            int b = row >> 10;
            uint32_t word = packh2(so[2 * d], so[2 * d + 1]);
            Kp[((size_t)(b * NKV + (h - NH)) * SS + s) * (HD/2) + d] = word;
        }
    }
}

// ==================== fp16 tensor-core flash attention (unchanged from R14) =========
#define QW 68
#define KW 68
#define VW 136
#define FL_SMEM ((128*QW + 2*64*KW + 2*32*VW) * 4)   // 104448 B

__global__ __launch_bounds__(256, 2) void flash_h(const __half* __restrict__ Qh,
                                                  const uint32_t* __restrict__ Kp,
                                                  const uint32_t* __restrict__ Vp,
                                                  __half* __restrict__ O) {
    extern __shared__ uint32_t smu[];
    uint32_t* Qs = smu;
    uint32_t* Ks = Qs + 128 * QW;
    uint32_t* Vs = Ks + 2 * 64 * KW;

    const int qi   = (int)gridDim.x - 1 - (int)blockIdx.x;
    const int h    = blockIdx.y;
    const int b    = blockIdx.z;
    const int kvh  = h >> 2;
    const int tid  = threadIdx.x;
    const int lane = tid & 31;
    const int w    = tid >> 5;
    const int g    = lane >> 2;
    const int tg   = lane & 3;
    const int qs   = qi * 128;
    const int ntiles = 2 * qi + 2;
    const float scl = 0.08838834764831845f * 1.4426950408889634f;

    const __half*   Qg = Qh + (size_t)(b * SS + qs) * (NH * HD) + h * HD;
    const uint32_t* Kg = Kp + (size_t)(b * NKV + kvh) * SS * (HD/2);
    const uint32_t* Vg = Vp + (size_t)(b * NKV + kvh) * (SS/2) * HD;

#pragma unroll
    for (int it = 0; it < 8; ++it) {
        int e = tid + it * 256;
        int r = e >> 4, c = e & 15;
        unsigned d = (unsigned)__cvta_generic_to_shared(Qs + r * QW + c * 4);
        CP_ASYNC16(d, Qg + (size_t)r * (NH * HD) + c * 8);
    }
#pragma unroll
    for (int it = 0; it < 4; ++it) {
        int e = tid + it * 256;
        int r = e >> 4, c = e & 15;
        unsigned d = (unsigned)__cvta_generic_to_shared(Ks + r * KW + c * 4);
        CP_ASYNC16(d, Kg + (size_t)r * (HD/2) + c * 4);
    }
#pragma unroll
    for (int it = 0; it < 4; ++it) {
        int e = tid + it * 256;
        int r = e >> 5, c = e & 31;
        unsigned d = (unsigned)__cvta_generic_to_shared(Vs + r * VW + c * 4);
        CP_ASYNC16(d, Vg + (size_t)r * HD + c * 4);
    }
    CP_COMMIT();

    float m0 = -1e30f, m1 = -1e30f, l0 = 0.f, l1 = 0.f;
    float acc[16][4];
#pragma unroll
    for (int nt = 0; nt < 16; ++nt)
#pragma unroll
        for (int c = 0; c < 4; ++c) acc[nt][c] = 0.f;

    const int rowg0 = qs + w * 16 + g;
    const int rowg1 = rowg0 + 8;

    for (int kt = 0; kt < ntiles; ++kt) {
        __syncthreads();
        if (kt + 1 < ntiles) {
            int bf = (kt + 1) & 1;
            uint32_t* Kw2 = Ks + bf * 64 * KW;
            uint32_t* Vw2 = Vs + bf * 32 * VW;
            const uint32_t* kg = Kg + (size_t)(kt + 1) * 64 * (HD/2);
            const uint32_t* vg = Vg + (size_t)(kt + 1) * 32 * HD;
#pragma unroll
            for (int it = 0; it < 4; ++it) {
                int e = tid + it * 256;
                int r = e >> 4, c = e & 15;
                unsigned d = (unsigned)__cvta_generic_to_shared(Kw2 + r * KW + c * 4);
                CP_ASYNC16(d, kg + (size_t)r * (HD/2) + c * 4);
            }
#pragma unroll
            for (int it = 0; it < 4; ++it) {
                int e = tid + it * 256;
                int r = e >> 5, c = e & 31;
                unsigned d = (unsigned)__cvta_generic_to_shared(Vw2 + r * VW + c * 4);
                CP_ASYNC16(d, vg + (size_t)r * HD + c * 4);
            }
            CP_COMMIT();
            CP_WAIT1();
        } else {
            CP_WAIT0();
        }
        __syncthreads();

        const uint32_t* Kb = Ks + (kt & 1) * 64 * KW;
        const uint32_t* Vb = Vs + (kt & 1) * 32 * VW;

        float sacc[8][4];
#pragma unroll
        for (int nt = 0; nt < 8; ++nt)
#pragma unroll
            for (int c = 0; c < 4; ++c) sacc[nt][c] = 0.f;

#pragma unroll
        for (int ks = 0; ks < 8; ++ks) {
            const uint32_t* qp = Qs + (size_t)(w * 16 + g) * QW + ks * 8 + tg;
            uint32_t a0 = qp[0];
            uint32_t a1 = qp[8 * QW];
            uint32_t a2 = qp[4];
            uint32_t a3 = qp[8 * QW + 4];
#pragma unroll
            for (int nt = 0; nt < 8; ++nt) {
                const uint32_t* kp = Kb + (size_t)(nt * 8 + g) * KW + ks * 8 + tg;
                mma_f16(sacc[nt][0], sacc[nt][1], sacc[nt][2], sacc[nt][3],
                        a0, a1, a2, a3, kp[0], kp[4]);
            }
        }

        const bool need_mask = (kt >= 2 * qi);
        float mx0 = -1e30f, mx1 = -1e30f;
#pragma unroll
        for (int nt = 0; nt < 8; ++nt) {
            int c0 = kt * 64 + nt * 8 + 2 * tg;
            int c1 = c0 + 1;
            float v0 = sacc[nt][0] * scl, v1 = sacc[nt][1] * scl;
            float v2 = sacc[nt][2] * scl, v3 = sacc[nt][3] * scl;
            if (need_mask) {
                if (c0 > rowg0) v0 = -1e30f;
                if (c1 > rowg0) v1 = -1e30f;
                if (c0 > rowg1) v2 = -1e30f;
                if (c1 > rowg1) v3 = -1e30f;
            }
            sacc[nt][0] = v0; sacc[nt][1] = v1; sacc[nt][2] = v2; sacc[nt][3] = v3;
            mx0 = fmaxf(mx0, fmaxf(v0, v1));
            mx1 = fmaxf(mx1, fmaxf(v2, v3));
        }
        mx0 = fmaxf(mx0, __shfl_xor_sync(0xffffffffu, mx0, 1));
        mx0 = fmaxf(mx0, __shfl_xor_sync(0xffffffffu, mx0, 2));
        mx1 = fmaxf(mx1, __shfl_xor_sync(0xffffffffu, mx1, 1));
        mx1 = fmaxf(mx1, __shfl_xor_sync(0xffffffffu, mx1, 2));

        float mn0 = fmaxf(m0, mx0), mn1 = fmaxf(m1, mx1);
        float al0 = exp2f(m0 - mn0), al1 = exp2f(m1 - mn1);
        m0 = mn0; m1 = mn1;

        float ps0 = 0.f, ps1 = 0.f;
#pragma unroll
        for (int nt = 0; nt < 8; ++nt) {
            float p0 = exp2f(sacc[nt][0] - mn0);
            float p1 = exp2f(sacc[nt][1] - mn0);
            float p2 = exp2f(sacc[nt][2] - mn1);
            float p3 = exp2f(sacc[nt][3] - mn1);
            ps0 += p0 + p1; ps1 += p2 + p3;
            sacc[nt][0] = p0; sacc[nt][1] = p1;
            sacc[nt][2] = p2; sacc[nt][3] = p3;
        }
        ps0 += __shfl_xor_sync(0xffffffffu, ps0, 1);
        ps0 += __shfl_xor_sync(0xffffffffu, ps0, 2);
        ps1 += __shfl_xor_sync(0xffffffffu, ps1, 1);
        ps1 += __shfl_xor_sync(0xffffffffu, ps1, 2);
        l0 = l0 * al0 + ps0;
        l1 = l1 * al1 + ps1;

#pragma unroll
        for (int nt = 0; nt < 16; ++nt) {
            acc[nt][0] *= al0; acc[nt][1] *= al0;
            acc[nt][2] *= al1; acc[nt][3] *= al1;
        }

#pragma unroll
        for (int ks = 0; ks < 4; ++ks) {
            uint32_t a0 = packh2(sacc[2*ks][0],   sacc[2*ks][1]);
            uint32_t a1 = packh2(sacc[2*ks][2],   sacc[2*ks][3]);
            uint32_t a2 = packh2(sacc[2*ks+1][0], sacc[2*ks+1][1]);
            uint32_t a3 = packh2(sacc[2*ks+1][2], sacc[2*ks+1][3]);
#pragma unroll
            for (int nt = 0; nt < 16; ++nt) {
                const uint32_t* vp = Vb + (size_t)(ks * 8 + tg) * VW + nt * 8 + g;
                mma_f16(acc[nt][0], acc[nt][1], acc[nt][2], acc[nt][3],
                        a0, a1, a2, a3, vp[0], vp[4 * VW]);
            }
        }
    }

    float inv0 = 1.0f / l0, inv1 = 1.0f / l1;
    __half* Og = O + (size_t)(b * SS + qs + w * 16) * (NH * HD) + h * HD;
#pragma unroll
    for (int nt = 0; nt < 16; ++nt) {
        int col = nt * 8 + 2 * tg;
        uint32_t h0 = packh2(acc[nt][0] * inv0, acc[nt][1] * inv0);
        uint32_t h1 = packh2(acc[nt][2] * inv1, acc[nt][3] * inv1);
        *(uint32_t*)(Og + (size_t)g * (NH * HD) + col)       = h0;
        *(uint32_t*)(Og + (size_t)(g + 8) * (NH * HD) + col) = h1;
    }
}

// -------------------- launch --------------------
extern "C" void kernel_launch(void* const* d_in, const int* in_sizes, int n_in,
                              void* d_out, int out_size) {
    const float* x  = (const float*)d_in[0];
    const float* wq = (const float*)d_in[1];
    const float* wk = (const float*)d_in[2];
    const float* wv = (const float*)d_in[3];
    const float* wo = (const float*)d_in[4];
    const float* qw = (const float*)d_in[5];
    const float* kw = (const float*)d_in[6];
    float* out = (float*)d_out;

    float *qkv; __half *qh, *ctx, *xh; uint32_t *kp, *vp, *wp;
    cudaGetSymbolAddress((void**)&qkv, g_qkv);
    cudaGetSymbolAddress((void**)&qh,  g_qh);
    cudaGetSymbolAddress((void**)&kp,  g_kh);
    cudaGetSymbolAddress((void**)&vp,  g_vh);
    cudaGetSymbolAddress((void**)&ctx, g_ctx);
    cudaGetSymbolAddress((void**)&xh,  g_xh);
    cudaGetSymbolAddress((void**)&wp,  g_wp);

    cudaFuncSetAttribute(gemm_f16, cudaFuncAttributeMaxDynamicSharedMemorySize, GEMM_SMEM);
    cudaFuncSetAttribute(flash_h,  cudaFuncAttributeMaxDynamicSharedMemorySize, FL_SMEM);

    // fp16 activations + rope tables
    pack_x<<<(MROWS * HH / 4) / 256, 256>>>(x, xh);
    rope_table_kernel<<<64, 1024>>>();

    // transposed packed weights: wp[n][kp], n in [0,6144) = [wq | wk | wv]
    pack_weight_t<<<dim3(4096/32, 2048/32), 256>>>(wq, wp, 4096, HH/2, 0);
    pack_weight_t<<<dim3(1024/32, 2048/32), 256>>>(wk, wp, 1024, HH/2, KOFF);
    pack_weight_t<<<dim3(1024/32, 2048/32), 256>>>(wv, wp, 1024, HH/2, VOFF);

    // fused QKV projection (fp16 mma + ldmatrix)
    gemm_f16<<<dim3(QKVN / 128, 16), 256, GEMM_SMEM>>>(xh, wp, qkv, MROWS, QKVN, HH);

    // RMSNorm + RoPE -> Q fp16 rows, K packed words; V -> packed words
    norm_rope_kernel<<<dim3(MROWS, NH + NKV), 128>>>(qkv, qh, kp, qw, kw);
    v_pack<<<(BB * NKV * (SS/2) * HD) / 256, 256>>>(qkv, vp);

    // causal GQA attention (fp16 tensor cores)
    flash_h<<<dim3(SS / 128, NH, BB), 256, FL_SMEM>>>(qh, kp, vp, ctx);

    // output projection
    pack_weight_t<<<dim3(4096/32, 2048/32), 256>>>(wo, wp, 4096, HH/2, 0);
    gemm_f16<<<dim3(32, 16), 256, GEMM_SMEM>>>(ctx, wp, out, MROWS, 4096, 4096);
}

// round 17
// speedup vs baseline: 2.9489x; 1.0154x over previous
#include <cuda_runtime.h>
#include <cuda_fp16.h>
#include <math.h>
#include <stdint.h>

// Problem constants
#define BB   2
#define SS   1024
#define HH   4096
#define NH   32
#define NKV  8
#define HD   128
#define MROWS (BB*SS)             // 2048
#define QKVN (NH*HD + 2*NKV*HD)   // 6144 fused QKV width
#define KOFF (NH*HD)              // 4096
#define VOFF (NH*HD + NKV*HD)     // 5120

// -------------------- scratch (device globals; no allocation) --------------------
__device__ float    g_qkv[MROWS * QKVN];        // fused Q|K|V fp32 (GEMM out)
__device__ __half   g_qh [MROWS * NH * HD];     // Q fp16 rows (post norm+rope)
__device__ uint32_t g_kh [BB*NKV * SS * (HD/2)];   // K packed {d,d+1}: [bh][key][dp]
__device__ uint32_t g_vh [BB*NKV * (SS/2) * HD];   // V packed {k,k+1}: [bh][kp][d]
__device__ __half   g_ctx[MROWS * NH * HD];     // ctx fp16 (feeds wo GEMM)
__device__ __half   g_xh [MROWS * HH];          // fp16 x
__device__ uint32_t g_wp [QKVN * (HH/2)];       // packed TRANSPOSED weights [n][kp]
__device__ float    g_cos[SS * (HD/2)];
__device__ float    g_sin[SS * (HD/2)];

// fp16 tensor-core mma: D(16x8,f32) += A(16x16,f16) * B(16x8,f16)
__device__ __forceinline__ void mma_f16(float& d0, float& d1, float& d2, float& d3,
                                        uint32_t a0, uint32_t a1, uint32_t a2, uint32_t a3,
                                        uint32_t b0, uint32_t b1) {
    asm volatile("mma.sync.aligned.m16n8k16.row.col.f32.f16.f16.f32 "
                 "{%0,%1,%2,%3},{%4,%5,%6,%7},{%8,%9},{%0,%1,%2,%3};"
                 : "+f"(d0), "+f"(d1), "+f"(d2), "+f"(d3)
                 : "r"(a0), "r"(a1), "r"(a2), "r"(a3), "r"(b0), "r"(b1));
}

__device__ __forceinline__ void ldsm_x4(uint32_t& r0, uint32_t& r1,
                                        uint32_t& r2, uint32_t& r3, uint32_t addr) {
    asm volatile("ldmatrix.sync.aligned.m8n8.x4.shared.b16 {%0,%1,%2,%3}, [%4];"
                 : "=r"(r0), "=r"(r1), "=r"(r2), "=r"(r3) : "r"(addr));
}

__device__ __forceinline__ uint32_t packh2(float lo, float hi) {
    __half2 h = __floats2half2_rn(lo, hi);
    return *(uint32_t*)&h;
}

// two fp16 exp2 in one MUFU op
__device__ __forceinline__ uint32_t ex2h2(uint32_t x) {
    uint32_t r;
    asm("ex2.approx.f16x2 %0, %1;" : "=r"(r) : "r"(x));
    return r;
}

#define CP_ASYNC16(saddr, gptr) \
    asm volatile("cp.async.cg.shared.global [%0], [%1], 16;" :: "r"(saddr), "l"(gptr))
#define CP_COMMIT() asm volatile("cp.async.commit_group;")
#define CP_WAIT1()  asm volatile("cp.async.wait_group 1;")
#define CP_WAIT0()  asm volatile("cp.async.wait_group 0;")

// ==================== FP16 GEMM, ldmatrix fragments (3-stage, 2 CTA/SM) =============
#define ASTW 20
#define BSTN 20
#define STGW (128*ASTW + 128*BSTN)         // 5120 u32 = 20480 B
#define GEMM_SMEM (3 * STGW * 4)           // 61440 B

__device__ __forceinline__ void stage_tile(int tid, uint32_t* smbase,
                                           const __half* __restrict__ Ag,
                                           const uint32_t* __restrict__ Bg,
                                           int Kp2, int K, int t) {
    uint32_t* As = smbase + (t % 3) * STGW;
    uint32_t* Bs = As + 128 * ASTW;
#pragma unroll
    for (int i = 0; i < 2; ++i) {
        int e = tid + i * 256;
        int r = e >> 2, c = e & 3;
        unsigned d = (unsigned)__cvta_generic_to_shared(As + r * ASTW + c * 4);
        CP_ASYNC16(d, Ag + (size_t)r * K + t * 32 + c * 8);
    }
#pragma unroll
    for (int i = 0; i < 2; ++i) {
        int e = tid + i * 256;
        int r = e >> 2, c = e & 3;
        unsigned d = (unsigned)__cvta_generic_to_shared(Bs + r * BSTN + c * 4);
        CP_ASYNC16(d, Bg + (size_t)r * Kp2 + t * 16 + c * 4);
    }
    CP_COMMIT();
}

__global__ __launch_bounds__(256, 2) void gemm_f16(const __half* __restrict__ A,
                                                   const uint32_t* __restrict__ Bt,
                                                   float* __restrict__ C,
                                                   int M, int N, int K) {
    extern __shared__ uint32_t smw[];

    const int tid  = threadIdx.x;
    const int lane = tid & 31;
    const int w    = tid >> 5;
    const int g    = lane >> 2;
    const int tg   = lane & 3;
    const int wm   = (w & 1) * 64;
    const int wn   = (w >> 1) * 32;
    const int bm   = blockIdx.y * 128;
    const int bn   = blockIdx.x * 128;

    const int aRow = lane & 15;
    const int aOff = (lane >> 4) * 4;
    const int bRow = (lane & 7) + ((lane >> 4) & 1) * 8;
    const int bOff = ((lane >> 3) & 1) * 4;

    const int Kp2 = K >> 1;
    const __half*   Ag = A  + (size_t)bm * K;
    const uint32_t* Bg = Bt + (size_t)bn * Kp2;
    const int T = K >> 5;
    const uint32_t sbase = (uint32_t)__cvta_generic_to_shared(smw);

    stage_tile(tid, smw, Ag, Bg, Kp2, K, 0);
    stage_tile(tid, smw, Ag, Bg, Kp2, K, 1);

    float acc[4][4][4];
#pragma unroll
    for (int mi = 0; mi < 4; ++mi)
#pragma unroll
        for (int ni = 0; ni < 4; ++ni)
#pragma unroll
            for (int c = 0; c < 4; ++c) acc[mi][ni][c] = 0.f;

    for (int t = 0; t < T; ++t) {
        if (t < T - 1) CP_WAIT1();
        else           CP_WAIT0();
        __syncthreads();
        if (t + 2 < T) stage_tile(tid, smw, Ag, Bg, Kp2, K, t + 2);

        const uint32_t Ab = sbase + ((t % 3) * STGW) * 4;
        const uint32_t Bb = Ab + 128 * ASTW * 4;
        const uint32_t aBase = Ab + ((wm + aRow) * ASTW + aOff) * 4;
        const uint32_t bBase = Bb + ((wn + bRow) * BSTN + bOff) * 4;

#pragma unroll
        for (int ks = 0; ks < 2; ++ks) {
            uint32_t af[4][4], bf[4][2];
#pragma unroll
            for (int mi = 0; mi < 4; ++mi)
                ldsm_x4(af[mi][0], af[mi][1], af[mi][2], af[mi][3],
                        aBase + (mi * 16 * ASTW + ks * 8) * 4);
#pragma unroll
            for (int np = 0; np < 2; ++np)
                ldsm_x4(bf[2*np][0], bf[2*np][1], bf[2*np+1][0], bf[2*np+1][1],
                        bBase + (np * 16 * BSTN + ks * 8) * 4);
#pragma unroll
            for (int mi = 0; mi < 4; ++mi)
#pragma unroll
                for (int ni = 0; ni < 4; ++ni)
                    mma_f16(acc[mi][ni][0], acc[mi][ni][1], acc[mi][ni][2], acc[mi][ni][3],
                            af[mi][0], af[mi][1], af[mi][2], af[mi][3],
                            bf[ni][0], bf[ni][1]);
        }
    }

#pragma unroll
    for (int mi = 0; mi < 4; ++mi) {
        int r0 = bm + wm + mi * 16 + g;
#pragma unroll
        for (int ni = 0; ni < 4; ++ni) {
            int c0 = bn + wn + ni * 8 + 2 * tg;
            float2 v0 = {acc[mi][ni][0], acc[mi][ni][1]};
            float2 v1 = {acc[mi][ni][2], acc[mi][ni][3]};
            *(float2*)(C + (size_t)r0 * N + c0)       = v0;
            *(float2*)(C + (size_t)(r0 + 8) * N + c0) = v1;
        }
    }
}

// -------------------- x -> fp16 copy --------------------
__global__ void pack_x(const float* __restrict__ in, __half* __restrict__ outp) {
    int i = blockIdx.x * 256 + threadIdx.x;
    float4 v = ((const float4*)in)[i];
    uint2 u = {packh2(v.x, v.y), packh2(v.z, v.w)};
    ((uint2*)outp)[i] = u;
}

// -------------------- weight -> packed TRANSPOSED half2 words --------------------
__global__ __launch_bounds__(256) void pack_weight_t(const float* __restrict__ in,
                                                     uint32_t* __restrict__ outp,
                                                     int Nw, int Kp2out, int off) {
    __shared__ uint32_t ts[32][33];
    const int n0  = blockIdx.x * 32;
    const int kp0 = blockIdx.y * 32;
    const int tx = threadIdx.x & 31, ty = threadIdx.x >> 5;
#pragma unroll
    for (int i = 0; i < 4; ++i) {
        int kp = kp0 + ty + i * 8;
        float r0 = in[(size_t)(2 * kp)     * Nw + n0 + tx];
        float r1 = in[(size_t)(2 * kp + 1) * Nw + n0 + tx];
        ts[ty + i * 8][tx] = packh2(r0, r1);
    }
    __syncthreads();
#pragma unroll
    for (int i = 0; i < 4; ++i) {
        int nl = ty + i * 8;
        outp[(size_t)(off + n0 + nl) * Kp2out + kp0 + tx] = ts[tx][nl];
    }
}

// -------------------- V -> packed {key,key+1} half2 words --------------------
__global__ void v_pack(const float* __restrict__ QKV, uint32_t* __restrict__ outp) {
    int i = blockIdx.x * 256 + threadIdx.x;
    int d   = i & (HD - 1);
    int kp  = (i >> 7) & (SS/2 - 1);
    int bh  = i >> 16;
    int b   = bh >> 3, kvh = bh & 7;
    size_t base = (size_t)(b * SS + 2 * kp) * QKVN + VOFF + kvh * HD + d;
    float v0 = QKV[base];
    float v1 = QKV[base + QKVN];
    outp[i] = packh2(v0, v1);
}

// -------------------- RoPE cos/sin table --------------------
__global__ __launch_bounds__(1024) void rope_table_kernel() {
    __shared__ double sinv[64];
    const int tid = threadIdx.x;
    if (tid < 64) sinv[tid] = exp(-(double)tid / 64.0 * log(10000.0));
    __syncthreads();
    const int f = tid & 63;
    const int s = blockIdx.x * 16 + (tid >> 6);
    double a = (double)s * sinv[f];
    double q = rint(a * 0.15915494309189535);
    float r = (float)(a - q * 6.283185307179586);
    float sc, cc;
    __sincosf(r, &sc, &cc);
    g_cos[s * 64 + f] = cc;
    g_sin[s * 64 + f] = sc;
}

// -------------------- fused RMSNorm + RoPE -> fp16 outputs --------------------
__global__ __launch_bounds__(128) void norm_rope_kernel(const float* __restrict__ QKV,
                                                        __half* __restrict__ Qh,
                                                        uint32_t* __restrict__ Kp,
                                                        const float* __restrict__ qw,
                                                        const float* __restrict__ kw) {
    const int row = blockIdx.x;
    const int h   = blockIdx.y;
    const int d   = threadIdx.x;

    const float* ptr;
    const float* w;
    if (h < NH) { ptr = QKV + (size_t)row * QKVN + h * HD;               w = qw; }
    else        { ptr = QKV + (size_t)row * QKVN + KOFF + (h - NH) * HD; w = kw; }

    float v = ptr[d];
    float ss = v * v;
#pragma unroll
    for (int o = 16; o > 0; o >>= 1) ss += __shfl_xor_sync(0xffffffffu, ss, o);

    __shared__ float wsum[4];
    if ((d & 31) == 0) wsum[d >> 5] = ss;
    __syncthreads();
    float tot = wsum[0] + wsum[1] + wsum[2] + wsum[3];
    float rn  = rsqrtf(tot * (1.0f / 128.0f) + 1e-6f);
    float vn  = v * rn * w[d];

    __shared__ float sv[128];
    sv[d] = vn;
    __syncthreads();

    const int s = row & (SS - 1);
    const int i = d & 63;
    float c  = g_cos[s * 64 + i];
    float sn = g_sin[s * 64 + i];
    float t1 = sv[i];
    float t2 = sv[i + 64];
    float out = (d < 64) ? (t1 * c - t2 * sn) : (t1 * sn + t2 * c);

    if (h < NH) {
        Qh[(size_t)row * (NH * HD) + h * HD + d] = __float2half(out);
    } else {
        __shared__ float so[128];
        so[d] = out;
        __syncthreads();
        if (d < 64) {
            int b = row >> 10;
            uint32_t word = packh2(so[2 * d], so[2 * d + 1]);
            Kp[((size_t)(b * NKV + (h - NH)) * SS + s) * (HD/2) + d] = word;
        }
    }
}

// ==================== fp16 flash attention: ldmatrix + f16x2 exp + mma row-sums =====
#define QW 68
#define KW 68
#define VW 136
#define FL_SMEM ((128*QW + 2*64*KW + 2*32*VW) * 4)   // 104448 B

__global__ __launch_bounds__(256, 2) void flash_h(const __half* __restrict__ Qh,
                                                  const uint32_t* __restrict__ Kp,
                                                  const uint32_t* __restrict__ Vp,
                                                  __half* __restrict__ O) {
    extern __shared__ uint32_t smu[];
    uint32_t* Qs = smu;
    uint32_t* Ks = Qs + 128 * QW;
    uint32_t* Vs = Ks + 2 * 64 * KW;

    const int qi   = (int)gridDim.x - 1 - (int)blockIdx.x;
    const int h    = blockIdx.y;
    const int b    = blockIdx.z;
    const int kvh  = h >> 2;
    const int tid  = threadIdx.x;
    const int lane = tid & 31;
    const int w    = tid >> 5;
    const int g    = lane >> 2;
    const int tg   = lane & 3;
    const int qs   = qi * 128;
    const int ntiles = 2 * qi + 2;
    const float scl = 0.08838834764831845f * 1.4426950408889634f;
    const uint32_t ONES = 0x3C003C00u;   // half2 {1, 1}

    // ldmatrix per-lane addressing (same mapping as gemm_f16, validated)
    const int aRow = lane & 15;
    const int aOff = (lane >> 4) * 4;
    const int bRow = (lane & 7) + ((lane >> 4) & 1) * 8;
    const int bOff = ((lane >> 3) & 1) * 4;

    const __half*   Qg = Qh + (size_t)(b * SS + qs) * (NH * HD) + h * HD;
    const uint32_t* Kg = Kp + (size_t)(b * NKV + kvh) * SS * (HD/2);
    const uint32_t* Vg = Vp + (size_t)(b * NKV + kvh) * (SS/2) * HD;

    const uint32_t sflat = (uint32_t)__cvta_generic_to_shared(smu);
    const uint32_t qBase = sflat + ((w * 16 + aRow) * QW + aOff) * 4;
    const uint32_t kFlat = sflat + 128 * QW * 4;

#pragma unroll
    for (int it = 0; it < 8; ++it) {
        int e = tid + it * 256;
        int r = e >> 4, c = e & 15;
        unsigned d = (unsigned)__cvta_generic_to_shared(Qs + r * QW + c * 4);
        CP_ASYNC16(d, Qg + (size_t)r * (NH * HD) + c * 8);
    }
#pragma unroll
    for (int it = 0; it < 4; ++it) {
        int e = tid + it * 256;
        int r = e >> 4, c = e & 15;
        unsigned d = (unsigned)__cvta_generic_to_shared(Ks + r * KW + c * 4);
        CP_ASYNC16(d, Kg + (size_t)r * (HD/2) + c * 4);
    }
#pragma unroll
    for (int it = 0; it < 4; ++it) {
        int e = tid + it * 256;
        int r = e >> 5, c = e & 31;
        unsigned d = (unsigned)__cvta_generic_to_shared(Vs + r * VW + c * 4);
        CP_ASYNC16(d, Vg + (size_t)r * HD + c * 4);
    }
    CP_COMMIT();

    float m0 = -1e30f, m1 = -1e30f;
    float lacc[4] = {0.f, 0.f, 0.f, 0.f};   // row sums via ones-mma
    float acc[16][4];
#pragma unroll
    for (int nt = 0; nt < 16; ++nt)
#pragma unroll
        for (int c = 0; c < 4; ++c) acc[nt][c] = 0.f;

    const int rowg0 = qs + w * 16 + g;
    const int rowg1 = rowg0 + 8;

    for (int kt = 0; kt < ntiles; ++kt) {
        __syncthreads();
        if (kt + 1 < ntiles) {
            int bf = (kt + 1) & 1;
            uint32_t* Kw2 = Ks + bf * 64 * KW;
            uint32_t* Vw2 = Vs + bf * 32 * VW;
            const uint32_t* kg = Kg + (size_t)(kt + 1) * 64 * (HD/2);
            const uint32_t* vg = Vg + (size_t)(kt + 1) * 32 * HD;
#pragma unroll
            for (int it = 0; it < 4; ++it) {
                int e = tid + it * 256;
                int r = e >> 4, c = e & 15;
                unsigned d = (unsigned)__cvta_generic_to_shared(Kw2 + r * KW + c * 4);
                CP_ASYNC16(d, kg + (size_t)r * (HD/2) + c * 4);
            }
#pragma unroll
            for (int it = 0; it < 4; ++it) {
                int e = tid + it * 256;
                int r = e >> 5, c = e & 31;
                unsigned d = (unsigned)__cvta_generic_to_shared(Vw2 + r * VW + c * 4);
                CP_ASYNC16(d, vg + (size_t)r * HD + c * 4);
            }
            CP_COMMIT();
            CP_WAIT1();
        } else {
            CP_WAIT0();
        }
        __syncthreads();

        const uint32_t kBase = kFlat + ((kt & 1) * 64 * KW + bRow * KW + bOff) * 4;
        const uint32_t* Vb = Vs + (kt & 1) * 32 * VW;

        // ---- S = Q @ K^T via ldmatrix (8 k16 steps over HD=128)
        float sacc[8][4];
#pragma unroll
        for (int nt = 0; nt < 8; ++nt)
#pragma unroll
            for (int c = 0; c < 4; ++c) sacc[nt][c] = 0.f;

#pragma unroll
        for (int ks = 0; ks < 8; ++ks) {
            uint32_t a0, a1, a2, a3;
            ldsm_x4(a0, a1, a2, a3, qBase + ks * 8 * 4);
            uint32_t bf2[8][2];
#pragma unroll
            for (int np = 0; np < 4; ++np)
                ldsm_x4(bf2[2*np][0], bf2[2*np][1], bf2[2*np+1][0], bf2[2*np+1][1],
                        kBase + (np * 16 * KW + ks * 8) * 4);
#pragma unroll
            for (int nt = 0; nt < 8; ++nt)
                mma_f16(sacc[nt][0], sacc[nt][1], sacc[nt][2], sacc[nt][3],
                        a0, a1, a2, a3, bf2[nt][0], bf2[nt][1]);
        }

        // ---- online softmax: mask, row-max, f16x2 exp2 -> packed P
        const bool need_mask = (kt >= 2 * qi);
        float mx0 = -1e30f, mx1 = -1e30f;
#pragma unroll
        for (int nt = 0; nt < 8; ++nt) {
            int c0 = kt * 64 + nt * 8 + 2 * tg;
            int c1 = c0 + 1;
            float v0 = sacc[nt][0] * scl, v1 = sacc[nt][1] * scl;
            float v2 = sacc[nt][2] * scl, v3 = sacc[nt][3] * scl;
            if (need_mask) {
                if (c0 > rowg0) v0 = -1e30f;
                if (c1 > rowg0) v1 = -1e30f;
                if (c0 > rowg1) v2 = -1e30f;
                if (c1 > rowg1) v3 = -1e30f;
            }
            sacc[nt][0] = v0; sacc[nt][1] = v1; sacc[nt][2] = v2; sacc[nt][3] = v3;
            mx0 = fmaxf(mx0, fmaxf(v0, v1));
            mx1 = fmaxf(mx1, fmaxf(v2, v3));
        }
        mx0 = fmaxf(mx0, __shfl_xor_sync(0xffffffffu, mx0, 1));
        mx0 = fmaxf(mx0, __shfl_xor_sync(0xffffffffu, mx0, 2));
        mx1 = fmaxf(mx1, __shfl_xor_sync(0xffffffffu, mx1, 1));
        mx1 = fmaxf(mx1, __shfl_xor_sync(0xffffffffu, mx1, 2));

        float mn0 = fmaxf(m0, mx0), mn1 = fmaxf(m1, mx1);
        float al0 = exp2f(m0 - mn0), al1 = exp2f(m1 - mn1);
        m0 = mn0; m1 = mn1;

        uint32_t pw[8][2];
#pragma unroll
        for (int nt = 0; nt < 8; ++nt) {
            pw[nt][0] = ex2h2(packh2(sacc[nt][0] - mn0, sacc[nt][1] - mn0));
            pw[nt][1] = ex2h2(packh2(sacc[nt][2] - mn1, sacc[nt][3] - mn1));
        }

        // rescale O acc and l acc
#pragma unroll
        for (int nt = 0; nt < 16; ++nt) {
            acc[nt][0] *= al0; acc[nt][1] *= al0;
            acc[nt][2] *= al1; acc[nt][3] *= al1;
        }
        lacc[0] *= al0; lacc[1] *= al0; lacc[2] *= al1; lacc[3] *= al1;

        // ---- O += P @ V ; l += P @ ones (tensor-core row sums)
#pragma unroll
        for (int ks = 0; ks < 4; ++ks) {
            uint32_t a0 = pw[2*ks][0];
            uint32_t a1 = pw[2*ks][1];
            uint32_t a2 = pw[2*ks+1][0];
            uint32_t a3 = pw[2*ks+1][1];
            mma_f16(lacc[0], lacc[1], lacc[2], lacc[3], a0, a1, a2, a3, ONES, ONES);
#pragma unroll
            for (int nt = 0; nt < 16; ++nt) {
                const uint32_t* vp = Vb + (size_t)(ks * 8 + tg) * VW + nt * 8 + g;
                mma_f16(acc[nt][0], acc[nt][1], acc[nt][2], acc[nt][3],
                        a0, a1, a2, a3, vp[0], vp[4 * VW]);
            }
        }
    }

    float inv0 = 1.0f / lacc[0], inv1 = 1.0f / lacc[2];
    __half* Og = O + (size_t)(b * SS + qs + w * 16) * (NH * HD) + h * HD;
#pragma unroll
    for (int nt = 0; nt < 16; ++nt) {
        int col = nt * 8 + 2 * tg;
        uint32_t h0 = packh2(acc[nt][0] * inv0, acc[nt][1] * inv0);
        uint32_t h1 = packh2(acc[nt][2] * inv1, acc[nt][3] * inv1);
        *(uint32_t*)(Og + (size_t)g * (NH * HD) + col)       = h0;
        *(uint32_t*)(Og + (size_t)(g + 8) * (NH * HD) + col) = h1;
    }
}

// -------------------- launch --------------------
extern "C" void kernel_launch(void* const* d_in, const int* in_sizes, int n_in,
                              void* d_out, int out_size) {
    const float* x  = (const float*)d_in[0];
    const float* wq = (const float*)d_in[1];
    const float* wk = (const float*)d_in[2];
    const float* wv = (const float*)d_in[3];
    const float* wo = (const float*)d_in[4];
    const float* qw = (const float*)d_in[5];
    const float* kw = (const float*)d_in[6];
    float* out = (float*)d_out;

    float *qkv; __half *qh, *ctx, *xh; uint32_t *kp, *vp, *wp;
    cudaGetSymbolAddress((void**)&qkv, g_qkv);
    cudaGetSymbolAddress((void**)&qh,  g_qh);
    cudaGetSymbolAddress((void**)&kp,  g_kh);
    cudaGetSymbolAddress((void**)&vp,  g_vh);
    cudaGetSymbolAddress((void**)&ctx, g_ctx);
    cudaGetSymbolAddress((void**)&xh,  g_xh);
    cudaGetSymbolAddress((void**)&wp,  g_wp);

    cudaFuncSetAttribute(gemm_f16, cudaFuncAttributeMaxDynamicSharedMemorySize, GEMM_SMEM);
    cudaFuncSetAttribute(flash_h,  cudaFuncAttributeMaxDynamicSharedMemorySize, FL_SMEM);

    // fp16 activations + rope tables
    pack_x<<<(MROWS * HH / 4) / 256, 256>>>(x, xh);
    rope_table_kernel<<<64, 1024>>>();

    // transposed packed weights: wp[n][kp], n in [0,6144) = [wq | wk | wv]
    pack_weight_t<<<dim3(4096/32, 2048/32), 256>>>(wq, wp, 4096, HH/2, 0);
    pack_weight_t<<<dim3(1024/32, 2048/32), 256>>>(wk, wp, 1024, HH/2, KOFF);
    pack_weight_t<<<dim3(1024/32, 2048/32), 256>>>(wv, wp, 1024, HH/2, VOFF);

    // fused QKV projection (fp16 mma + ldmatrix)
    gemm_f16<<<dim3(QKVN / 128, 16), 256, GEMM_SMEM>>>(xh, wp, qkv, MROWS, QKVN, HH);

    // RMSNorm + RoPE -> Q fp16 rows, K packed words; V -> packed words
    norm_rope_kernel<<<dim3(MROWS, NH + NKV), 128>>>(qkv, qh, kp, qw, kw);
    v_pack<<<(BB * NKV * (SS/2) * HD) / 256, 256>>>(qkv, vp);

    // causal GQA attention (fp16 tensor cores, f16x2 softmax)
    flash_h<<<dim3(SS / 128, NH, BB), 256, FL_SMEM>>>(qh, kp, vp, ctx);

    // output projection
    pack_weight_t<<<dim3(4096/32, 2048/32), 256>>>(wo, wp, 4096, HH/2, 0);
    gemm_f16<<<dim3(32, 16), 256, GEMM_SMEM>>>(ctx, wp, out, MROWS, 4096, 4096);
}